// round 1
// baseline (speedup 1.0000x reference)
#include <cuda_runtime.h>
#include <math.h>

#define DN 16384
#define DL 10
#define DD 256
#define DH2 2
#define DDH 128
#define S_PER 32
#define NTHR 256

// Precomputed fused weights (per-launch, deterministic)
__device__ __align__(16) float g_G[DD][2 * DD];   // [e][h*256+d] = sum_j wq[h*128+j][e]*wk[h*128+j][d]
__device__ __align__(16) float g_W[2 * DD][DD];   // [h*256+e][d] = sum_j w_out[d][h*128+j]*wv[h*128+j][e]
__device__ __align__(16) float g_r[2 * DD];       // [h*256+d]    = sum_j wk[h*128+j][d]*bq[h*128+j]
__device__ __align__(16) float g_bo[DD];          // b_out[d] + sum_c w_out[d][c]*bv[c]

// ---------------- precompute kernels ----------------

__global__ void pre_G(const float* __restrict__ w_in) {
    int e  = blockIdx.x;            // 0..255
    int k0 = threadIdx.x * 4;       // 0..508, 128 threads
    int h  = k0 >> 8;
    int d0 = k0 & 255;
    const float* wq = w_in + (size_t)(h * DDH) * DD;
    const float* wk = w_in + (size_t)(DD + h * DDH) * DD;
    float a0 = 0.f, a1 = 0.f, a2 = 0.f, a3 = 0.f;
#pragma unroll 4
    for (int j = 0; j < DDH; j++) {
        float a  = wq[j * DD + e];
        float4 b = *reinterpret_cast<const float4*>(&wk[j * DD + d0]);
        a0 = fmaf(a, b.x, a0); a1 = fmaf(a, b.y, a1);
        a2 = fmaf(a, b.z, a2); a3 = fmaf(a, b.w, a3);
    }
    float4 r; r.x = a0; r.y = a1; r.z = a2; r.w = a3;
    *reinterpret_cast<float4*>(&g_G[e][k0]) = r;
}

__global__ void pre_W(const float* __restrict__ w_in, const float* __restrict__ w_out) {
    int k = blockIdx.x;             // 0..511
    int h = k >> 8;
    int e = k & 255;
    __shared__ float sv[DDH];
    int t = threadIdx.x;            // 256 threads
    if (t < DDH) sv[t] = w_in[(size_t)(2 * DD + h * DDH + t) * DD + e];
    __syncthreads();
    int d = t;
    const float4* wo4 = reinterpret_cast<const float4*>(w_out + (size_t)d * DD + h * DDH);
    float acc = 0.f;
#pragma unroll 8
    for (int jj = 0; jj < DDH / 4; jj++) {
        float4 b = wo4[jj];
        acc = fmaf(sv[4 * jj + 0], b.x, acc);
        acc = fmaf(sv[4 * jj + 1], b.y, acc);
        acc = fmaf(sv[4 * jj + 2], b.z, acc);
        acc = fmaf(sv[4 * jj + 3], b.w, acc);
    }
    g_W[k][d] = acc;
}

__global__ void pre_small(const float* __restrict__ w_in, const float* __restrict__ b_in,
                          const float* __restrict__ w_out, const float* __restrict__ b_out) {
    int t = threadIdx.x;            // 256
    if (blockIdx.x < 2) {
        int h = blockIdx.x, d = t;
        float a = 0.f;
        for (int j = 0; j < DDH; j++)
            a = fmaf(w_in[(size_t)(DD + h * DDH + j) * DD + d], b_in[h * DDH + j], a);
        g_r[h * DD + d] = a;
    } else {
        int d = t;
        float a = b_out[d];
        for (int c = 0; c < DD; c++)
            a = fmaf(w_out[(size_t)d * DD + c], b_in[2 * DD + c], a);
        g_bo[d] = a;
    }
}

// ---------------- main fused kernel ----------------

struct SM {
    float ml[S_PER][DD];         // m_last per sequence
    float U[S_PER][2 * DD];      // u (then reused as mbar)
    float ts[S_PER][DL];
    float sc[S_PER][DH2][DL];
    float attn[S_PER][DH2][DL];
    float wt[DD];
    float bt[DD];
};

__global__ void __launch_bounds__(NTHR, 2) attn_main(
    const float* __restrict__ msgs, const float* __restrict__ tstamp,
    const float* __restrict__ w_time, const float* __restrict__ b_time,
    const int* __restrict__ lengths, float* __restrict__ out)
{
    extern __shared__ char smem_raw[];
    SM& s = *reinterpret_cast<SM*>(smem_raw);
    const int tid = threadIdx.x;
    const int n0  = blockIdx.x * S_PER;

    // stage inputs
    s.wt[tid] = w_time[tid];
    s.bt[tid] = b_time[tid];
    for (int i = tid; i < S_PER * DD; i += NTHR) {
        int ss = i >> 8, d = i & 255;
        s.ml[ss][d] = msgs[((size_t)(n0 + ss) * DL + (DL - 1)) * DD + d];
    }
    for (int i = tid; i < S_PER * DL; i += NTHR)
        s.ts[i / DL][i % DL] = tstamp[(size_t)(n0 + i / DL) * DL + i % DL];
    __syncthreads();

    // ---- GEMM1: U[s][k] = sum_e ml[s][e] * G[e][k]  (+ bias fold r) ----
    {
        const int sb = (tid >> 6) * 8;
        const int kb = (tid & 63) * 8;
        float acc[8][8];
#pragma unroll
        for (int i = 0; i < 8; i++)
#pragma unroll
            for (int j = 0; j < 8; j++) acc[i][j] = 0.f;
        for (int e = 0; e < DD; e++) {
            float4 gA = *reinterpret_cast<const float4*>(&g_G[e][kb]);
            float4 gB = *reinterpret_cast<const float4*>(&g_G[e][kb + 4]);
            float gg[8] = {gA.x, gA.y, gA.z, gA.w, gB.x, gB.y, gB.z, gB.w};
#pragma unroll
            for (int i = 0; i < 8; i++) {
                float m = s.ml[sb + i][e];
#pragma unroll
                for (int j = 0; j < 8; j++) acc[i][j] = fmaf(m, gg[j], acc[i][j]);
            }
        }
#pragma unroll
        for (int i = 0; i < 8; i++)
#pragma unroll
            for (int j = 0; j < 8; j++)
                s.U[sb + i][kb + j] = acc[i][j] + g_r[kb + j];
    }
    __syncthreads();

    // ---- scores: sc[s][h][l] = (u_h . te_l) / sqrt(DH) ----
    const float scale = 0.08838834764831845f;  // 1/sqrt(128)
    for (int it = tid; it < S_PER * DL; it += NTHR) {
        int ss = it / DL, l = it % DL;
        float delta = s.ts[ss][l] - s.ts[ss][DL - 1];
        float a0 = 0.f, a1 = 0.f;
#pragma unroll 4
        for (int d = 0; d < DD; d++) {
            float c = cosf(fmaf(delta, s.wt[d], s.bt[d]));
            a0 = fmaf(c, s.U[ss][d], a0);
            a1 = fmaf(c, s.U[ss][DD + d], a1);
        }
        s.sc[ss][0][l] = a0 * scale;
        s.sc[ss][1][l] = a1 * scale;
    }
    __syncthreads();

    // ---- masked softmax over l (10 elems) ----
    if (tid < S_PER * DH2) {
        int ss = tid >> 1, h = tid & 1;
        int len = lengths[n0 + ss];
        int pad = DL - (len + 1);          // positions l < pad masked
        float v[DL];
        float mx = -3.4e38f;
#pragma unroll
        for (int l = 0; l < DL; l++) {
            float x = (l < pad) ? -1e9f : s.sc[ss][h][l];
            v[l] = x;
            mx = fmaxf(mx, x);
        }
        float sum = 0.f;
#pragma unroll
        for (int l = 0; l < DL; l++) { v[l] = expf(v[l] - mx); sum += v[l]; }
        float inv = 1.f / sum;
#pragma unroll
        for (int l = 0; l < DL; l++) s.attn[ss][h][l] = v[l] * inv;
    }
    __syncthreads();

    // ---- mbar[s][h*256+e] = sum_l attn[s][h][l] * msg[s][l][e]  (overwrite U) ----
    for (int it = tid; it < S_PER * DD; it += NTHR) {
        int ss = it >> 8, e = it & 255;
        const float* mrow = msgs + (size_t)(n0 + ss) * DL * DD + e;
        float a0 = 0.f, a1 = 0.f;
#pragma unroll
        for (int l = 0; l < DL; l++) {
            float v = __ldg(mrow + l * DD);
            a0 = fmaf(s.attn[ss][0][l], v, a0);
            a1 = fmaf(s.attn[ss][1][l], v, a1);
        }
        s.U[ss][e]      = a0;
        s.U[ss][DD + e] = a1;
    }
    __syncthreads();

    // ---- GEMM2: out[s][d] = bo[d] + sum_k mbar[s][k] * W[k][d] ----
    {
        const int sb = (tid >> 6) * 8;
        const int db = (tid & 63) * 4;
        float acc[8][4];
#pragma unroll
        for (int i = 0; i < 8; i++)
#pragma unroll
            for (int j = 0; j < 4; j++) acc[i][j] = 0.f;
        for (int k = 0; k < 2 * DD; k++) {
            float4 w = *reinterpret_cast<const float4*>(&g_W[k][db]);
#pragma unroll
            for (int i = 0; i < 8; i++) {
                float m = s.U[sb + i][k];
                acc[i][0] = fmaf(m, w.x, acc[i][0]);
                acc[i][1] = fmaf(m, w.y, acc[i][1]);
                acc[i][2] = fmaf(m, w.z, acc[i][2]);
                acc[i][3] = fmaf(m, w.w, acc[i][3]);
            }
        }
        float4 bo = *reinterpret_cast<const float4*>(&g_bo[db]);
#pragma unroll
        for (int i = 0; i < 8; i++) {
            float4 r;
            r.x = acc[i][0] + bo.x;
            r.y = acc[i][1] + bo.y;
            r.z = acc[i][2] + bo.z;
            r.w = acc[i][3] + bo.w;
            *reinterpret_cast<float4*>(&out[(size_t)(n0 + sb + i) * DD + db]) = r;
        }
    }
}

// ---------------- launch ----------------

extern "C" void kernel_launch(void* const* d_in, const int* in_sizes, int n_in,
                              void* d_out, int out_size) {
    const float* msgs   = (const float*)d_in[0];
    const float* ts     = (const float*)d_in[1];
    const float* w_time = (const float*)d_in[2];
    const float* b_time = (const float*)d_in[3];
    const float* w_in   = (const float*)d_in[4];
    const float* b_in   = (const float*)d_in[5];
    const float* w_out  = (const float*)d_in[6];
    const float* b_out  = (const float*)d_in[7];
    const int*   lengths = (const int*)d_in[8];
    float* out = (float*)d_out;

    cudaFuncSetAttribute(attn_main, cudaFuncAttributeMaxDynamicSharedMemorySize,
                         (int)sizeof(SM));

    pre_G<<<DD, 128>>>(w_in);
    pre_W<<<2 * DD, 256>>>(w_in, w_out);
    pre_small<<<3, 256>>>(w_in, b_in, w_out, b_out);
    attn_main<<<DN / S_PER, NTHR, sizeof(SM)>>>(msgs, ts, w_time, b_time, lengths, out);
}

// round 2
// speedup vs baseline: 1.4099x; 1.4099x over previous
#include <cuda_runtime.h>
#include <math.h>

#define DN 16384
#define DL 10
#define DD 256
#define DH2 2
#define DDH 128
#define S_PER 32
#define NTHR 256

typedef unsigned long long u64;

// Precomputed fused weights (per-launch, deterministic)
__device__ __align__(16) float g_G[DD][2 * DD];   // [e][h*256+d] = sum_j wq[h*128+j][e]*wk[h*128+j][d]
__device__ __align__(16) float g_W[2 * DD][DD];   // [h*256+e][d] = sum_j w_out[d][h*128+j]*wv[h*128+j][e]
__device__ __align__(16) float g_r[2 * DD];       // [h*256+d]    = sum_j wk[h*128+j][d]*bq[h*128+j]
__device__ __align__(16) float g_bo[DD];          // b_out[d] + sum_c w_out[d][c]*bv[c]

// ---------------- f32x2 helpers ----------------

__device__ __forceinline__ u64 dup2(float x) {
    u64 r; asm("mov.b64 %0, {%1,%1};" : "=l"(r) : "f"(x)); return r;
}
__device__ __forceinline__ void ffma2(u64& acc, u64 a, u64 b) {
    asm("fma.rn.f32x2 %0, %1, %2, %0;" : "+l"(acc) : "l"(a), "l"(b));
}
__device__ __forceinline__ u64 fadd2(u64 a, u64 b) {
    u64 r; asm("add.rn.f32x2 %0, %1, %2;" : "=l"(r) : "l"(a), "l"(b)); return r;
}

// ---------------- precompute kernels ----------------

__global__ void pre_G(const float* __restrict__ w_in) {
    int e  = blockIdx.x;            // 0..255
    int k0 = threadIdx.x * 4;       // 0..508, 128 threads
    int h  = k0 >> 8;
    int d0 = k0 & 255;
    const float* wq = w_in + (size_t)(h * DDH) * DD;
    const float* wk = w_in + (size_t)(DD + h * DDH) * DD;
    float a0 = 0.f, a1 = 0.f, a2 = 0.f, a3 = 0.f;
#pragma unroll 4
    for (int j = 0; j < DDH; j++) {
        float a  = wq[j * DD + e];
        float4 b = *reinterpret_cast<const float4*>(&wk[j * DD + d0]);
        a0 = fmaf(a, b.x, a0); a1 = fmaf(a, b.y, a1);
        a2 = fmaf(a, b.z, a2); a3 = fmaf(a, b.w, a3);
    }
    float4 r; r.x = a0; r.y = a1; r.z = a2; r.w = a3;
    *reinterpret_cast<float4*>(&g_G[e][k0]) = r;
}

__global__ void pre_W(const float* __restrict__ w_in, const float* __restrict__ w_out) {
    int k = blockIdx.x;             // 0..511
    int h = k >> 8;
    int e = k & 255;
    __shared__ float sv[DDH];
    int t = threadIdx.x;            // 256 threads
    if (t < DDH) sv[t] = w_in[(size_t)(2 * DD + h * DDH + t) * DD + e];
    __syncthreads();
    int d = t;
    const float4* wo4 = reinterpret_cast<const float4*>(w_out + (size_t)d * DD + h * DDH);
    float acc = 0.f;
#pragma unroll 8
    for (int jj = 0; jj < DDH / 4; jj++) {
        float4 b = wo4[jj];
        acc = fmaf(sv[4 * jj + 0], b.x, acc);
        acc = fmaf(sv[4 * jj + 1], b.y, acc);
        acc = fmaf(sv[4 * jj + 2], b.z, acc);
        acc = fmaf(sv[4 * jj + 3], b.w, acc);
    }
    g_W[k][d] = acc;
}

__global__ void pre_small(const float* __restrict__ w_in, const float* __restrict__ b_in,
                          const float* __restrict__ w_out, const float* __restrict__ b_out) {
    int t = threadIdx.x;            // 256
    if (blockIdx.x < 2) {
        int h = blockIdx.x, d = t;
        float a = 0.f;
        for (int j = 0; j < DDH; j++)
            a = fmaf(w_in[(size_t)(DD + h * DDH + j) * DD + d], b_in[h * DDH + j], a);
        g_r[h * DD + d] = a;
    } else {
        int d = t;
        float a = b_out[d];
        for (int c = 0; c < DD; c++)
            a = fmaf(w_out[(size_t)d * DD + c], b_in[2 * DD + c], a);
        g_bo[d] = a;
    }
}

// ---------------- main fused kernel ----------------

struct SM {
    float ml[S_PER][DD];         // m_last per sequence
    float U[S_PER][2 * DD];      // u (then reused as mbar)
    float ts[S_PER][DL];
    float sc[S_PER][DH2][DL];
    float attn[S_PER][DH2][DL];
    float wt[DD];
    float bt[DD];
};

__global__ void __launch_bounds__(NTHR, 2) attn_main(
    const float* __restrict__ msgs, const float* __restrict__ tstamp,
    const float* __restrict__ w_time, const float* __restrict__ b_time,
    const int* __restrict__ lengths, float* __restrict__ out)
{
    extern __shared__ char smem_raw[];
    SM& s = *reinterpret_cast<SM*>(smem_raw);
    const int tid = threadIdx.x;
    const int n0  = blockIdx.x * S_PER;

    // stage inputs
    s.wt[tid] = w_time[tid];
    s.bt[tid] = b_time[tid];
    for (int i = tid; i < S_PER * DD; i += NTHR) {
        int ss = i >> 8, d = i & 255;
        s.ml[ss][d] = msgs[((size_t)(n0 + ss) * DL + (DL - 1)) * DD + d];
    }
    for (int i = tid; i < S_PER * DL; i += NTHR)
        s.ts[i / DL][i % DL] = tstamp[(size_t)(n0 + i / DL) * DL + i % DL];
    __syncthreads();

    // ---- GEMM1: U[s][k] = sum_e ml[s][e] * G[e][k]  (+ bias fold r), f32x2 ----
    {
        const int sb = (tid >> 6) * 8;
        const int kb = (tid & 63) * 8;
        u64 acc[8][4];
#pragma unroll
        for (int i = 0; i < 8; i++)
#pragma unroll
            for (int j = 0; j < 4; j++) acc[i][j] = 0ull;

        // row stride of g_G in ulonglong2 units: 512 floats = 128 ulonglong2
        const ulonglong2* gp = reinterpret_cast<const ulonglong2*>(&g_G[0][kb]);
        ulonglong2 p0 = gp[0],       p1 = gp[1];        // e = 0
        ulonglong2 q0 = gp[128],     q1 = gp[129];      // e = 1
        for (int e = 0; e < DD; e++) {
            ulonglong2 c0 = p0, c1 = p1;
            p0 = q0; p1 = q1;
            if (e + 2 < DD) {
                const ulonglong2* nx = gp + (size_t)(e + 2) * 128;
                q0 = nx[0]; q1 = nx[1];
            }
            u64 g0 = c0.x, g1 = c0.y, g2 = c1.x, g3 = c1.y;
#pragma unroll
            for (int i = 0; i < 8; i++) {
                u64 m = dup2(s.ml[sb + i][e]);
                ffma2(acc[i][0], m, g0);
                ffma2(acc[i][1], m, g1);
                ffma2(acc[i][2], m, g2);
                ffma2(acc[i][3], m, g3);
            }
        }
        const u64* r2 = reinterpret_cast<const u64*>(&g_r[kb]);
        u64 r0 = r2[0], r1 = r2[1], r2b = r2[2], r3 = r2[3];
#pragma unroll
        for (int i = 0; i < 8; i++) {
            ulonglong2* dst = reinterpret_cast<ulonglong2*>(&s.U[sb + i][kb]);
            ulonglong2 o0, o1;
            o0.x = fadd2(acc[i][0], r0); o0.y = fadd2(acc[i][1], r1);
            o1.x = fadd2(acc[i][2], r2b); o1.y = fadd2(acc[i][3], r3);
            dst[0] = o0; dst[1] = o1;
        }
    }
    __syncthreads();

    // ---- scores: sc[s][h][l] = (u_h . te_l) / sqrt(DH) ----
    const float scale = 0.08838834764831845f;  // 1/sqrt(128)
    for (int it = tid; it < S_PER * DL; it += NTHR) {
        int ss = it / DL, l = it % DL;
        float delta = s.ts[ss][l] - s.ts[ss][DL - 1];
        float a0 = 0.f, a1 = 0.f;
#pragma unroll 4
        for (int d = 0; d < DD; d++) {
            float c = __cosf(fmaf(delta, s.wt[d], s.bt[d]));
            a0 = fmaf(c, s.U[ss][d], a0);
            a1 = fmaf(c, s.U[ss][DD + d], a1);
        }
        s.sc[ss][0][l] = a0 * scale;
        s.sc[ss][1][l] = a1 * scale;
    }
    __syncthreads();

    // ---- masked softmax over l (10 elems) ----
    if (tid < S_PER * DH2) {
        int ss = tid >> 1, h = tid & 1;
        int len = lengths[n0 + ss];
        int pad = DL - (len + 1);          // positions l < pad masked
        float v[DL];
        float mx = -3.4e38f;
#pragma unroll
        for (int l = 0; l < DL; l++) {
            float x = (l < pad) ? -1e9f : s.sc[ss][h][l];
            v[l] = x;
            mx = fmaxf(mx, x);
        }
        float sum = 0.f;
#pragma unroll
        for (int l = 0; l < DL; l++) { v[l] = __expf(v[l] - mx); sum += v[l]; }
        float inv = 1.f / sum;
#pragma unroll
        for (int l = 0; l < DL; l++) s.attn[ss][h][l] = v[l] * inv;
    }
    __syncthreads();

    // ---- mbar[s][h*256+e] = sum_l attn[s][h][l] * msg[s][l][e]  (overwrite U) ----
    for (int it = tid; it < S_PER * DD; it += NTHR) {
        int ss = it >> 8, e = it & 255;
        const float* mrow = msgs + (size_t)(n0 + ss) * DL * DD + e;
        float a0 = 0.f, a1 = 0.f;
#pragma unroll
        for (int l = 0; l < DL; l++) {
            float v = __ldg(mrow + l * DD);
            a0 = fmaf(s.attn[ss][0][l], v, a0);
            a1 = fmaf(s.attn[ss][1][l], v, a1);
        }
        s.U[ss][e]      = a0;
        s.U[ss][DD + e] = a1;
    }
    __syncthreads();

    // ---- GEMM2: out[s][d] = bo[d] + sum_k mbar[s][k] * W[k][d], f32x2 ----
    {
        const int sb = (tid >> 5) * 4;      // 8 groups of 4 sequences
        const int db = (tid & 31) * 8;      // 32 groups of 8 outputs
        u64 acc[4][4];
#pragma unroll
        for (int i = 0; i < 4; i++)
#pragma unroll
            for (int j = 0; j < 4; j++) acc[i][j] = 0ull;

        // row stride of g_W in ulonglong2 units: 256 floats = 64 ulonglong2
        const ulonglong2* wp = reinterpret_cast<const ulonglong2*>(&g_W[0][db]);
        ulonglong2 p0 = wp[0],   p1 = wp[1];
        ulonglong2 q0 = wp[64],  q1 = wp[65];
        for (int k = 0; k < 2 * DD; k++) {
            ulonglong2 c0 = p0, c1 = p1;
            p0 = q0; p1 = q1;
            if (k + 2 < 2 * DD) {
                const ulonglong2* nx = wp + (size_t)(k + 2) * 64;
                q0 = nx[0]; q1 = nx[1];
            }
            u64 w0 = c0.x, w1 = c0.y, w2 = c1.x, w3 = c1.y;
#pragma unroll
            for (int i = 0; i < 4; i++) {
                u64 m = dup2(s.U[sb + i][k]);
                ffma2(acc[i][0], m, w0);
                ffma2(acc[i][1], m, w1);
                ffma2(acc[i][2], m, w2);
                ffma2(acc[i][3], m, w3);
            }
        }
        const u64* bo2 = reinterpret_cast<const u64*>(&g_bo[db]);
        u64 b0 = bo2[0], b1 = bo2[1], b2 = bo2[2], b3 = bo2[3];
#pragma unroll
        for (int i = 0; i < 4; i++) {
            ulonglong2* dst = reinterpret_cast<ulonglong2*>(&out[(size_t)(n0 + sb + i) * DD + db]);
            ulonglong2 o0, o1;
            o0.x = fadd2(acc[i][0], b0); o0.y = fadd2(acc[i][1], b1);
            o1.x = fadd2(acc[i][2], b2); o1.y = fadd2(acc[i][3], b3);
            dst[0] = o0; dst[1] = o1;
        }
    }
}

// ---------------- launch ----------------

extern "C" void kernel_launch(void* const* d_in, const int* in_sizes, int n_in,
                              void* d_out, int out_size) {
    const float* msgs   = (const float*)d_in[0];
    const float* ts     = (const float*)d_in[1];
    const float* w_time = (const float*)d_in[2];
    const float* b_time = (const float*)d_in[3];
    const float* w_in   = (const float*)d_in[4];
    const float* b_in   = (const float*)d_in[5];
    const float* w_out  = (const float*)d_in[6];
    const float* b_out  = (const float*)d_in[7];
    const int*   lengths = (const int*)d_in[8];
    float* out = (float*)d_out;

    cudaFuncSetAttribute(attn_main, cudaFuncAttributeMaxDynamicSharedMemorySize,
                         (int)sizeof(SM));

    pre_G<<<DD, 128>>>(w_in);
    pre_W<<<2 * DD, 256>>>(w_in, w_out);
    pre_small<<<3, 256>>>(w_in, b_in, w_out, b_out);
    attn_main<<<DN / S_PER, NTHR, sizeof(SM)>>>(msgs, ts, w_time, b_time, lengths, out);
}

// round 4
// speedup vs baseline: 2.6704x; 1.8940x over previous
#include <cuda_runtime.h>
#include <cuda_bf16.h>
#include <cstdint>
#include <math.h>

#define DN 16384
#define DL 10
#define DD 256

// ======================= helpers =======================

__device__ __forceinline__ uint32_t smem_u32(const void* p) {
    uint32_t a;
    asm("{ .reg .u64 t; cvta.to.shared.u64 t, %1; cvt.u32.u64 %0, t; }" : "=r"(a) : "l"(p));
    return a;
}

__device__ __forceinline__ void ldsm4(uint32_t* r, uint32_t a) {
    asm volatile("ldmatrix.sync.aligned.m8n8.x4.shared.b16 {%0,%1,%2,%3}, [%4];"
                 : "=r"(r[0]), "=r"(r[1]), "=r"(r[2]), "=r"(r[3]) : "r"(a));
}

__device__ __forceinline__ void mma16816(float* c, const uint32_t* a, uint32_t b0, uint32_t b1) {
    asm volatile("mma.sync.aligned.m16n8k16.row.col.f32.bf16.bf16.f32 "
                 "{%0,%1,%2,%3}, {%4,%5,%6,%7}, {%8,%9}, {%0,%1,%2,%3};"
                 : "+f"(c[0]), "+f"(c[1]), "+f"(c[2]), "+f"(c[3])
                 : "r"(a[0]), "r"(a[1]), "r"(a[2]), "r"(a[3]), "r"(b0), "r"(b1));
}

__device__ __forceinline__ void split_bf16(float x, __nv_bfloat16& h, __nv_bfloat16& l) {
    h = __float2bfloat16(x);
    l = __float2bfloat16(x - __bfloat162float(h));
}

// ======================= globals (scratch) =======================

__device__ __align__(16) float g_G[DD][2 * DD];
__device__ __align__(16) float g_W[2 * DD][DD];
__device__ __align__(16) float g_r[2 * DD];
__device__ __align__(16) float g_bo[DD];

__device__ __align__(16) __nv_bfloat16 g_Gt_hi[2 * DD * DD];  // [512][256] (n-major, k contig)
__device__ __align__(16) __nv_bfloat16 g_Gt_lo[2 * DD * DD];
__device__ __align__(16) __nv_bfloat16 g_Wt_hi[DD * 2 * DD];  // [256][512]
__device__ __align__(16) __nv_bfloat16 g_Wt_lo[DD * 2 * DD];
__device__ __align__(16) __nv_bfloat16 g_Mh[(size_t)DN * DD];
__device__ __align__(16) __nv_bfloat16 g_Ml[(size_t)DN * DD];
__device__ __align__(16) float g_U[(size_t)DN * 2 * DD];
__device__ __align__(16) __nv_bfloat16 g_Mbh[(size_t)DN * 2 * DD];
__device__ __align__(16) __nv_bfloat16 g_Mbl[(size_t)DN * 2 * DD];

// ======================= precompute =======================

__global__ void pre_G(const float* __restrict__ w_in) {
    int e  = blockIdx.x;
    int k0 = threadIdx.x * 4;
    int h  = k0 >> 8;
    int d0 = k0 & 255;
    const float* wq = w_in + (size_t)(h * 128) * DD;
    const float* wk = w_in + (size_t)(DD + h * 128) * DD;
    float a0 = 0.f, a1 = 0.f, a2 = 0.f, a3 = 0.f;
#pragma unroll 4
    for (int j = 0; j < 128; j++) {
        float a  = wq[j * DD + e];
        float4 b = *reinterpret_cast<const float4*>(&wk[j * DD + d0]);
        a0 = fmaf(a, b.x, a0); a1 = fmaf(a, b.y, a1);
        a2 = fmaf(a, b.z, a2); a3 = fmaf(a, b.w, a3);
    }
    float4 r; r.x = a0; r.y = a1; r.z = a2; r.w = a3;
    *reinterpret_cast<float4*>(&g_G[e][k0]) = r;
}

__global__ void pre_W(const float* __restrict__ w_in, const float* __restrict__ w_out) {
    int d = blockIdx.x;                  // 256 blocks, 512 threads
    __shared__ float wo[DD];
    int t = threadIdx.x;
    if (t < DD) wo[t] = w_out[(size_t)d * DD + t];
    __syncthreads();
    int h = t >> 8, e = t & 255;
    const float* wv = w_in + (size_t)(2 * DD + h * 128) * DD + e;
    const float* wor = wo + h * 128;
    float acc = 0.f;
#pragma unroll 8
    for (int j = 0; j < 128; j++)
        acc = fmaf(wor[j], wv[(size_t)j * DD], acc);
    g_W[t][d] = acc;
}

__global__ void pre_small(const float* __restrict__ w_in, const float* __restrict__ b_in,
                          const float* __restrict__ w_out, const float* __restrict__ b_out) {
    int t = threadIdx.x;
    if (blockIdx.x < 2) {
        int h = blockIdx.x, d = t;
        float a = 0.f;
        for (int j = 0; j < 128; j++)
            a = fmaf(w_in[(size_t)(DD + h * 128 + j) * DD + d], b_in[h * 128 + j], a);
        g_r[h * DD + d] = a;
    } else {
        int d = t;
        float a = b_out[d];
        for (int c = 0; c < DD; c++)
            a = fmaf(w_out[(size_t)d * DD + c], b_in[2 * DD + c], a);
        g_bo[d] = a;
    }
}

// transpose + split: g_G[e][n] (256x512) -> Gt[n][e] (512x256)
__global__ void conv_G() {
    __shared__ float st[32][33];
    int n0 = blockIdx.x * 32, e0 = blockIdx.y * 32;
    int jr = threadIdx.x & 31, ir = threadIdx.x >> 5;
#pragma unroll
    for (int ii = 0; ii < 4; ii++)
        st[ir + ii * 8][jr] = g_G[e0 + ir + ii * 8][n0 + jr];
    __syncthreads();
#pragma unroll
    for (int ii = 0; ii < 4; ii++) {
        int n = n0 + ir + ii * 8, e = e0 + jr;
        __nv_bfloat16 h, l;
        split_bf16(st[jr][ir + ii * 8], h, l);
        g_Gt_hi[(size_t)n * DD + e] = h;
        g_Gt_lo[(size_t)n * DD + e] = l;
    }
}

// g_W[k][d] (512x256) -> Wt[d][k] (256x512)
__global__ void conv_W() {
    __shared__ float st[32][33];
    int k0 = blockIdx.x * 32, d0 = blockIdx.y * 32;
    int jr = threadIdx.x & 31, ir = threadIdx.x >> 5;
#pragma unroll
    for (int ii = 0; ii < 4; ii++)
        st[ir + ii * 8][jr] = g_W[k0 + ii * 8 + ir][d0 + jr];
    __syncthreads();
#pragma unroll
    for (int ii = 0; ii < 4; ii++) {
        int d = d0 + ir + ii * 8, k = k0 + jr;
        __nv_bfloat16 h, l;
        split_bf16(st[jr][ir + ii * 8], h, l);
        g_Wt_hi[(size_t)d * 2 * DD + k] = h;
        g_Wt_lo[(size_t)d * 2 * DD + k] = l;
    }
}

// last msg row -> bf16 hi/lo
__global__ void extract_M(const float* __restrict__ msgs) {
    int idx = blockIdx.x * 256 + threadIdx.x;      // 4096 blocks
    int n = idx >> 6, d4 = (idx & 63) * 4;
    float4 v = *reinterpret_cast<const float4*>(&msgs[((size_t)n * DL + (DL - 1)) * DD + d4]);
    __nv_bfloat16 h0, l0, h1, l1, h2, l2, h3, l3;
    split_bf16(v.x, h0, l0); split_bf16(v.y, h1, l1);
    split_bf16(v.z, h2, l2); split_bf16(v.w, h3, l3);
    __nv_bfloat16* ph = &g_Mh[(size_t)n * DD + d4];
    __nv_bfloat16* pl = &g_Ml[(size_t)n * DD + d4];
    ph[0] = h0; ph[1] = h1; ph[2] = h2; ph[3] = h3;
    pl[0] = l0; pl[1] = l1; pl[2] = l2; pl[3] = l3;
}

// ======================= HMMA GEMM =======================
// C[M,N] = A[M,KT] @ B[KT,N] via 3-pass bf16 split.  B given transposed: BT[n][k].
// CTA: 128x128 tile; 8 warps 2(m) x 4(n); warp 64x32; K chunk 64.
// smem rows padded to 144B (72 bf16) -> conflict-free ldmatrix.

#define SM_ROW 144
#define SM_BUF 18432           // 128 * 144
#define GEMM_SMEM (4 * SM_BUF) // 73728

template<int KT>
__device__ __forceinline__ void gemm_body(
    const __nv_bfloat16* __restrict__ Ah, const __nv_bfloat16* __restrict__ Al,
    const __nv_bfloat16* __restrict__ Bh, const __nv_bfloat16* __restrict__ Bl,
    const float* __restrict__ bias, float* __restrict__ C, int ldc)
{
    extern __shared__ char sm[];
    const int tid = threadIdx.x, lane = tid & 31, wid = tid >> 5;
    const int m0 = blockIdx.x * 128, n0 = blockIdx.y * 128;
    const int wm = (wid >> 2) * 64, wn = (wid & 3) * 32;

    char* sAh = sm;
    char* sAl = sm + SM_BUF;
    char* sBh = sm + 2 * SM_BUF;
    char* sBl = sm + 3 * SM_BUF;
    const uint32_t uAh = smem_u32(sAh), uAl = smem_u32(sAl);
    const uint32_t uBh = smem_u32(sBh), uBl = smem_u32(sBl);

    float acc[4][4][4];
#pragma unroll
    for (int a = 0; a < 4; a++)
#pragma unroll
        for (int b = 0; b < 4; b++)
#pragma unroll
            for (int cc = 0; cc < 4; cc++) acc[a][b][cc] = 0.f;

    for (int k0 = 0; k0 < KT; k0 += 64) {
        __syncthreads();
#pragma unroll
        for (int it = 0; it < 4; it++) {
            int idx = tid + it * 256;
            int r = idx >> 3, q = idx & 7;
            uint32_t so = (uint32_t)(r * SM_ROW + q * 16);
            size_t ga = (size_t)(m0 + r) * KT + k0 + q * 8;
            size_t gb = (size_t)(n0 + r) * KT + k0 + q * 8;
            *reinterpret_cast<uint4*>(sAh + so) = *reinterpret_cast<const uint4*>(Ah + ga);
            *reinterpret_cast<uint4*>(sAl + so) = *reinterpret_cast<const uint4*>(Al + ga);
            *reinterpret_cast<uint4*>(sBh + so) = *reinterpret_cast<const uint4*>(Bh + gb);
            *reinterpret_cast<uint4*>(sBl + so) = *reinterpret_cast<const uint4*>(Bl + gb);
        }
        __syncthreads();

#pragma unroll
        for (int kk = 0; kk < 4; kk++) {
            const uint32_t colb = (uint32_t)(kk * 32 + (lane >> 4) * 16);
            const uint32_t arow = (uint32_t)(wm + (lane & 15));
            uint32_t af[4][4], bh[2][4], bl[2][4];
#pragma unroll
            for (int mt = 0; mt < 4; mt++)
                ldsm4(af[mt], uAh + (arow + mt * 16) * SM_ROW + colb);
#pragma unroll
            for (int nt = 0; nt < 2; nt++) {
                uint32_t brow = (uint32_t)(wn + nt * 16 + (lane & 15));
                ldsm4(bh[nt], uBh + brow * SM_ROW + colb);
                ldsm4(bl[nt], uBl + brow * SM_ROW + colb);
            }
            // passes hi*hi and hi*lo (reuse A-hi fragments)
#pragma unroll
            for (int mt = 0; mt < 4; mt++)
#pragma unroll
                for (int ns = 0; ns < 4; ns++) {
                    mma16816(acc[mt][ns], af[mt], bh[ns >> 1][ns & 1], bh[ns >> 1][(ns & 1) + 2]);
                    mma16816(acc[mt][ns], af[mt], bl[ns >> 1][ns & 1], bl[ns >> 1][(ns & 1) + 2]);
                }
            // pass lo*hi (reload A-lo over A-hi regs)
#pragma unroll
            for (int mt = 0; mt < 4; mt++)
                ldsm4(af[mt], uAl + (arow + mt * 16) * SM_ROW + colb);
#pragma unroll
            for (int mt = 0; mt < 4; mt++)
#pragma unroll
                for (int ns = 0; ns < 4; ns++)
                    mma16816(acc[mt][ns], af[mt], bh[ns >> 1][ns & 1], bh[ns >> 1][(ns & 1) + 2]);
        }
    }

    // epilogue: direct global stores + bias
#pragma unroll
    for (int mt = 0; mt < 4; mt++) {
        int r0 = m0 + wm + mt * 16 + (lane >> 2);
#pragma unroll
        for (int ns = 0; ns < 4; ns++) {
            int c = n0 + wn + ns * 8 + (lane & 3) * 2;
            float2 b = *reinterpret_cast<const float2*>(bias + c);
            float2 v0, v1;
            v0.x = acc[mt][ns][0] + b.x; v0.y = acc[mt][ns][1] + b.y;
            v1.x = acc[mt][ns][2] + b.x; v1.y = acc[mt][ns][3] + b.y;
            *reinterpret_cast<float2*>(C + (size_t)r0 * ldc + c) = v0;
            *reinterpret_cast<float2*>(C + (size_t)(r0 + 8) * ldc + c) = v1;
        }
    }
}

__global__ void __launch_bounds__(256, 2) gemm1_k() {
    gemm_body<DD>(g_Mh, g_Ml, g_Gt_hi, g_Gt_lo, g_r, g_U, 2 * DD);
}
__global__ void __launch_bounds__(256, 2) gemm2_k(float* __restrict__ out) {
    gemm_body<2 * DD>(g_Mbh, g_Mbl, g_Wt_hi, g_Wt_lo, g_bo, out, DD);
}

// ======================= scores + softmax + aggregate =======================

__global__ void __launch_bounds__(256) score_agg(
    const float* __restrict__ msgs, const float* __restrict__ tstamp,
    const float* __restrict__ w_time, const float* __restrict__ b_time,
    const int* __restrict__ lengths)
{
    int wid = threadIdx.x >> 5, lane = threadIdx.x & 31;
    int s = blockIdx.x * 8 + wid;

    float wt[8], bt[8], u0[8], u1[8];
#pragma unroll
    for (int i = 0; i < 8; i++) {
        int d = lane + i * 32;
        wt[i] = w_time[d];
        bt[i] = b_time[d];
        u0[i] = g_U[(size_t)s * 512 + d];
        u1[i] = g_U[(size_t)s * 512 + 256 + d];
    }
    float ts9 = tstamp[(size_t)s * DL + (DL - 1)];
    const float scale = 0.08838834764831845f;

    float sc0[DL], sc1[DL];
#pragma unroll
    for (int l = 0; l < DL; l++) {
        float delta = tstamp[(size_t)s * DL + l] - ts9;
        float a0 = 0.f, a1 = 0.f;
#pragma unroll
        for (int i = 0; i < 8; i++) {
            float te = __cosf(fmaf(delta, wt[i], bt[i]));
            a0 = fmaf(te, u0[i], a0);
            a1 = fmaf(te, u1[i], a1);
        }
#pragma unroll
        for (int o = 16; o; o >>= 1) {
            a0 += __shfl_xor_sync(0xFFFFFFFF, a0, o);
            a1 += __shfl_xor_sync(0xFFFFFFFF, a1, o);
        }
        sc0[l] = a0 * scale;
        sc1[l] = a1 * scale;
    }

    int pad = DL - (lengths[s] + 1);
    float mx0 = -3.4e38f, mx1 = -3.4e38f;
#pragma unroll
    for (int l = 0; l < DL; l++) {
        sc0[l] = (l < pad) ? -1e9f : sc0[l];
        sc1[l] = (l < pad) ? -1e9f : sc1[l];
        mx0 = fmaxf(mx0, sc0[l]);
        mx1 = fmaxf(mx1, sc1[l]);
    }
    float sm0 = 0.f, sm1 = 0.f;
#pragma unroll
    for (int l = 0; l < DL; l++) {
        sc0[l] = __expf(sc0[l] - mx0); sm0 += sc0[l];
        sc1[l] = __expf(sc1[l] - mx1); sm1 += sc1[l];
    }
    float i0 = 1.f / sm0, i1 = 1.f / sm1;
#pragma unroll
    for (int l = 0; l < DL; l++) { sc0[l] *= i0; sc1[l] *= i1; }

#pragma unroll
    for (int i = 0; i < 8; i++) {
        int e = lane + i * 32;
        float m0 = 0.f, m1 = 0.f;
        const float* mp = msgs + (size_t)s * DL * DD + e;
#pragma unroll
        for (int l = 0; l < DL; l++) {
            float v = __ldg(mp + l * DD);
            m0 = fmaf(sc0[l], v, m0);
            m1 = fmaf(sc1[l], v, m1);
        }
        __nv_bfloat16 h, lo;
        split_bf16(m0, h, lo);
        g_Mbh[(size_t)s * 512 + e] = h;  g_Mbl[(size_t)s * 512 + e] = lo;
        split_bf16(m1, h, lo);
        g_Mbh[(size_t)s * 512 + 256 + e] = h;  g_Mbl[(size_t)s * 512 + 256 + e] = lo;
    }
}

// ======================= launch =======================

extern "C" void kernel_launch(void* const* d_in, const int* in_sizes, int n_in,
                              void* d_out, int out_size) {
    const float* msgs    = (const float*)d_in[0];
    const float* ts      = (const float*)d_in[1];
    const float* w_time  = (const float*)d_in[2];
    const float* b_time  = (const float*)d_in[3];
    const float* w_in    = (const float*)d_in[4];
    const float* b_in    = (const float*)d_in[5];
    const float* w_out   = (const float*)d_in[6];
    const float* b_out   = (const float*)d_in[7];
    const int*   lengths = (const int*)d_in[8];
    float* out = (float*)d_out;

    cudaFuncSetAttribute(gemm1_k, cudaFuncAttributeMaxDynamicSharedMemorySize, GEMM_SMEM);
    cudaFuncSetAttribute(gemm2_k, cudaFuncAttributeMaxDynamicSharedMemorySize, GEMM_SMEM);

    pre_G<<<DD, 128>>>(w_in);
    pre_W<<<DD, 512>>>(w_in, w_out);
    pre_small<<<3, 256>>>(w_in, b_in, w_out, b_out);
    conv_G<<<dim3(16, 8), 256>>>();
    conv_W<<<dim3(16, 8), 256>>>();
    extract_M<<<4096, 256>>>(msgs);
    gemm1_k<<<dim3(128, 4), 256, GEMM_SMEM>>>();
    score_agg<<<2048, 256>>>(msgs, ts, w_time, b_time, lengths);
    gemm2_k<<<dim3(128, 2), 256, GEMM_SMEM>>>(out);
}

// round 5
// speedup vs baseline: 3.2366x; 1.2120x over previous
#include <cuda_runtime.h>
#include <cuda_bf16.h>
#include <cstdint>
#include <math.h>

#define DN 16384
#define DL 10
#define DD 256

// ======================= helpers =======================

__device__ __forceinline__ uint32_t smem_u32(const void* p) {
    uint32_t a;
    asm("{ .reg .u64 t; cvta.to.shared.u64 t, %1; cvt.u32.u64 %0, t; }" : "=r"(a) : "l"(p));
    return a;
}

__device__ __forceinline__ void ldsm4(uint32_t* r, uint32_t a) {
    asm volatile("ldmatrix.sync.aligned.m8n8.x4.shared.b16 {%0,%1,%2,%3}, [%4];"
                 : "=r"(r[0]), "=r"(r[1]), "=r"(r[2]), "=r"(r[3]) : "r"(a));
}

__device__ __forceinline__ void mma16816(float* c, const uint32_t* a, uint32_t b0, uint32_t b1) {
    asm volatile("mma.sync.aligned.m16n8k16.row.col.f32.bf16.bf16.f32 "
                 "{%0,%1,%2,%3}, {%4,%5,%6,%7}, {%8,%9}, {%0,%1,%2,%3};"
                 : "+f"(c[0]), "+f"(c[1]), "+f"(c[2]), "+f"(c[3])
                 : "r"(a[0]), "r"(a[1]), "r"(a[2]), "r"(a[3]), "r"(b0), "r"(b1));
}

__device__ __forceinline__ void cp16(uint32_t s, const void* g) {
    asm volatile("cp.async.cg.shared.global [%0], [%1], 16;" :: "r"(s), "l"(g) : "memory");
}

__device__ __forceinline__ void split_bf16(float x, __nv_bfloat16& h, __nv_bfloat16& l) {
    h = __float2bfloat16(x);
    l = __float2bfloat16(x - __bfloat162float(h));
}

// ======================= globals (scratch) =======================

__device__ __align__(16) float g_r[2 * DD];
__device__ __align__(16) float g_bo[DD];

__device__ __align__(16) __nv_bfloat16 g_Gt_hi[2 * DD * DD];  // [512][256] (n-major, k contig)
__device__ __align__(16) __nv_bfloat16 g_Gt_lo[2 * DD * DD];
__device__ __align__(16) __nv_bfloat16 g_Wt_hi[DD * 2 * DD];  // [256][512]
__device__ __align__(16) __nv_bfloat16 g_Wt_lo[DD * 2 * DD];
__device__ __align__(16) __nv_bfloat16 g_Mh[(size_t)DN * DD];
__device__ __align__(16) __nv_bfloat16 g_Ml[(size_t)DN * DD];
__device__ __align__(16) float g_U[(size_t)DN * 2 * DD];
__device__ __align__(16) __nv_bfloat16 g_Mbh[(size_t)DN * 2 * DD];
__device__ __align__(16) __nv_bfloat16 g_Mbl[(size_t)DN * 2 * DD];

// ======================= fused precompute =======================
// blocks [0,128):    G^T hi/lo   (each block: 4 k-columns of Gt[512][256])
// blocks [128,384):  W^T hi/lo   (each block: one d row of Wt[256][512])
// blocks [384,387):  bias folds g_r, g_bo
// blocks [387,4483): extract last message row -> bf16 hi/lo

__global__ void __launch_bounds__(256) prep(
    const float* __restrict__ w_in, const float* __restrict__ b_in,
    const float* __restrict__ w_out, const float* __restrict__ b_out,
    const float* __restrict__ msgs)
{
    __shared__ float sbuf[128 * 4];
    const int b = blockIdx.x;
    const int t = threadIdx.x;

    if (b < 128) {
        // Gt[k][e] = sum_j wq_h[j][e] * wk_h[j][d],  k = h*256+d, 4 k per block
        const int k0 = b * 4;
        const int h  = k0 >> 8;
        const int d0 = k0 & 255;
        {
            int j = t >> 1, half = t & 1;
            const float* wk = w_in + (size_t)(DD + h * 128 + j) * DD + d0 + half * 2;
            sbuf[j * 4 + half * 2]     = wk[0];
            sbuf[j * 4 + half * 2 + 1] = wk[1];
        }
        __syncthreads();
        const int e = t;
        float a0 = 0.f, a1 = 0.f, a2 = 0.f, a3 = 0.f;
        const float* wq = w_in + (size_t)(h * 128) * DD + e;
#pragma unroll 4
        for (int j = 0; j < 128; j++) {
            float q = wq[(size_t)j * DD];
            a0 = fmaf(q, sbuf[j * 4 + 0], a0);
            a1 = fmaf(q, sbuf[j * 4 + 1], a1);
            a2 = fmaf(q, sbuf[j * 4 + 2], a2);
            a3 = fmaf(q, sbuf[j * 4 + 3], a3);
        }
        float acc[4] = {a0, a1, a2, a3};
#pragma unroll
        for (int kk = 0; kk < 4; kk++) {
            __nv_bfloat16 hh, ll;
            split_bf16(acc[kk], hh, ll);
            g_Gt_hi[(size_t)(k0 + kk) * DD + e] = hh;
            g_Gt_lo[(size_t)(k0 + kk) * DD + e] = ll;
        }
    } else if (b < 384) {
        // Wt[d][k] = sum_j w_out[d][h*128+j] * wv_h[j][e],  k = h*256+e
        const int d = b - 128;
        if (t < DD) sbuf[t] = w_out[(size_t)d * DD + t];
        __syncthreads();
#pragma unroll
        for (int rep = 0; rep < 2; rep++) {
            int k = t + rep * 256;
            int h = k >> 8, e = k & 255;
            const float* wv  = w_in + (size_t)(2 * DD + h * 128) * DD + e;
            const float* wor = sbuf + h * 128;
            float acc = 0.f;
#pragma unroll 8
            for (int j = 0; j < 128; j++)
                acc = fmaf(wor[j], wv[(size_t)j * DD], acc);
            __nv_bfloat16 hh, ll;
            split_bf16(acc, hh, ll);
            g_Wt_hi[(size_t)d * 512 + k] = hh;
            g_Wt_lo[(size_t)d * 512 + k] = ll;
        }
    } else if (b < 387) {
        int sb = b - 384;
        if (sb < 2) {
            int h = sb, d = t;
            float a = 0.f;
            for (int j = 0; j < 128; j++)
                a = fmaf(w_in[(size_t)(DD + h * 128 + j) * DD + d], b_in[h * 128 + j], a);
            g_r[h * DD + d] = a;
        } else {
            float a = b_out[t];
            for (int c = 0; c < DD; c++)
                a = fmaf(w_out[(size_t)t * DD + c], b_in[2 * DD + c], a);
            g_bo[t] = a;
        }
    } else {
        int idx = (b - 387) * 256 + t;
        int n = idx >> 6, d4 = (idx & 63) * 4;
        float4 v = *reinterpret_cast<const float4*>(&msgs[((size_t)n * DL + (DL - 1)) * DD + d4]);
        __nv_bfloat16 h0, l0, h1, l1, h2, l2, h3, l3;
        split_bf16(v.x, h0, l0); split_bf16(v.y, h1, l1);
        split_bf16(v.z, h2, l2); split_bf16(v.w, h3, l3);
        __nv_bfloat16* ph = &g_Mh[(size_t)n * DD + d4];
        __nv_bfloat16* pl = &g_Ml[(size_t)n * DD + d4];
        ph[0] = h0; ph[1] = h1; ph[2] = h2; ph[3] = h3;
        pl[0] = l0; pl[1] = l1; pl[2] = l2; pl[3] = l3;
    }
}

// ======================= HMMA GEMM (double-buffered cp.async) =======================
// C[M,N] = A[M,KT] @ B[KT,N], 3-pass bf16 split; B transposed: BT[n][k].
// CTA 128x128; 8 warps 2(m)x4(n); warp 64x32; K chunk 32, 2 stages.
// smem rows 80B (64B data + 16 pad) -> conflict-free ldmatrix.

#define SM_ROW 80
#define SM_BUF 10240            // 128*80
#define STAGE  (4 * SM_BUF)     // 40960
#define GEMM_SMEM (2 * STAGE)   // 81920

template<int KT>
__device__ __forceinline__ void gemm_body(
    const __nv_bfloat16* __restrict__ Ah, const __nv_bfloat16* __restrict__ Al,
    const __nv_bfloat16* __restrict__ Bh, const __nv_bfloat16* __restrict__ Bl,
    const float* __restrict__ bias, float* __restrict__ C, int ldc)
{
    extern __shared__ char sm[];
    const int tid = threadIdx.x, lane = tid & 31, wid = tid >> 5;
    const int m0 = blockIdx.x * 128, n0 = blockIdx.y * 128;
    const int wm = (wid >> 2) * 64, wn = (wid & 3) * 32;
    const uint32_t sbase = smem_u32(sm);

    // loader indices: 2 iters x (row, quad)
    const int r0q = (tid + 0)   >> 2, q0 = tid & 3;
    const int r1q = (tid + 256) >> 2, q1 = tid & 3;

    float acc[4][4][4];
#pragma unroll
    for (int a = 0; a < 4; a++)
#pragma unroll
        for (int bq = 0; bq < 4; bq++)
#pragma unroll
            for (int cc = 0; cc < 4; cc++) acc[a][bq][cc] = 0.f;

#define LOAD_STAGE(st, k0c) do { \
        uint32_t s0 = sbase + (st) * STAGE; \
        { uint32_t so = (uint32_t)(r0q * SM_ROW + q0 * 16); \
          size_t ga = (size_t)(m0 + r0q) * KT + (k0c) + q0 * 8; \
          size_t gb = (size_t)(n0 + r0q) * KT + (k0c) + q0 * 8; \
          cp16(s0 + so, Ah + ga); cp16(s0 + SM_BUF + so, Al + ga); \
          cp16(s0 + 2 * SM_BUF + so, Bh + gb); cp16(s0 + 3 * SM_BUF + so, Bl + gb); } \
        { uint32_t so = (uint32_t)(r1q * SM_ROW + q1 * 16); \
          size_t ga = (size_t)(m0 + r1q) * KT + (k0c) + q1 * 8; \
          size_t gb = (size_t)(n0 + r1q) * KT + (k0c) + q1 * 8; \
          cp16(s0 + so, Ah + ga); cp16(s0 + SM_BUF + so, Al + ga); \
          cp16(s0 + 2 * SM_BUF + so, Bh + gb); cp16(s0 + 3 * SM_BUF + so, Bl + gb); } \
        asm volatile("cp.async.commit_group;" ::: "memory"); \
    } while (0)

    LOAD_STAGE(0, 0);
    const int NC = KT / 32;
    for (int c = 0; c < NC; c++) {
        const int cur = c & 1;
        if (c + 1 < NC) {
            LOAD_STAGE(1 - cur, (c + 1) * 32);
            asm volatile("cp.async.wait_group 1;" ::: "memory");
        } else {
            asm volatile("cp.async.wait_group 0;" ::: "memory");
        }
        __syncthreads();

        const uint32_t uAh = sbase + cur * STAGE;
        const uint32_t uAl = uAh + SM_BUF;
        const uint32_t uBh = uAh + 2 * SM_BUF;
        const uint32_t uBl = uAh + 3 * SM_BUF;

#pragma unroll
        for (int kk = 0; kk < 2; kk++) {
            const uint32_t colb = (uint32_t)(kk * 32 + (lane >> 4) * 16);
            const uint32_t arow = (uint32_t)(wm + (lane & 15));
            uint32_t af[4][4], bh[2][4], bl[2][4];
#pragma unroll
            for (int mt = 0; mt < 4; mt++)
                ldsm4(af[mt], uAh + (arow + mt * 16) * SM_ROW + colb);
#pragma unroll
            for (int nt = 0; nt < 2; nt++) {
                uint32_t brow = (uint32_t)(wn + nt * 16 + (lane & 15));
                ldsm4(bh[nt], uBh + brow * SM_ROW + colb);
                ldsm4(bl[nt], uBl + brow * SM_ROW + colb);
            }
            // passes hi*hi and hi*lo (reuse A-hi fragments)
#pragma unroll
            for (int mt = 0; mt < 4; mt++)
#pragma unroll
                for (int ns = 0; ns < 4; ns++) {
                    mma16816(acc[mt][ns], af[mt], bh[ns >> 1][ns & 1], bh[ns >> 1][(ns & 1) + 2]);
                    mma16816(acc[mt][ns], af[mt], bl[ns >> 1][ns & 1], bl[ns >> 1][(ns & 1) + 2]);
                }
            // pass lo*hi (reload A-lo over A-hi regs)
#pragma unroll
            for (int mt = 0; mt < 4; mt++)
                ldsm4(af[mt], uAl + (arow + mt * 16) * SM_ROW + colb);
#pragma unroll
            for (int mt = 0; mt < 4; mt++)
#pragma unroll
                for (int ns = 0; ns < 4; ns++)
                    mma16816(acc[mt][ns], af[mt], bh[ns >> 1][ns & 1], bh[ns >> 1][(ns & 1) + 2]);
        }
        __syncthreads();
    }
#undef LOAD_STAGE

    // epilogue: direct global stores + bias
#pragma unroll
    for (int mt = 0; mt < 4; mt++) {
        int r0 = m0 + wm + mt * 16 + (lane >> 2);
#pragma unroll
        for (int ns = 0; ns < 4; ns++) {
            int cx = n0 + wn + ns * 8 + (lane & 3) * 2;
            float2 bb = *reinterpret_cast<const float2*>(bias + cx);
            float2 v0, v1;
            v0.x = acc[mt][ns][0] + bb.x; v0.y = acc[mt][ns][1] + bb.y;
            v1.x = acc[mt][ns][2] + bb.x; v1.y = acc[mt][ns][3] + bb.y;
            *reinterpret_cast<float2*>(C + (size_t)r0 * ldc + cx) = v0;
            *reinterpret_cast<float2*>(C + (size_t)(r0 + 8) * ldc + cx) = v1;
        }
    }
}

__global__ void __launch_bounds__(256, 2) gemm1_k() {
    gemm_body<DD>(g_Mh, g_Ml, g_Gt_hi, g_Gt_lo, g_r, g_U, 2 * DD);
}
__global__ void __launch_bounds__(256, 2) gemm2_k(float* __restrict__ out) {
    gemm_body<2 * DD>(g_Mbh, g_Mbl, g_Wt_hi, g_Wt_lo, g_bo, out, DD);
}

// ======================= scores + softmax + aggregate =======================

__global__ void __launch_bounds__(256) score_agg(
    const float* __restrict__ msgs, const float* __restrict__ tstamp,
    const float* __restrict__ w_time, const float* __restrict__ b_time,
    const int* __restrict__ lengths)
{
    int wid = threadIdx.x >> 5, lane = threadIdx.x & 31;
    int s = blockIdx.x * 8 + wid;

    float wt[8], bt[8], u0[8], u1[8];
#pragma unroll
    for (int i = 0; i < 8; i++) {
        int d = lane + i * 32;
        wt[i] = w_time[d];
        bt[i] = b_time[d];
        u0[i] = g_U[(size_t)s * 512 + d];
        u1[i] = g_U[(size_t)s * 512 + 256 + d];
    }
    float ts9 = tstamp[(size_t)s * DL + (DL - 1)];
    const float scale = 0.08838834764831845f;

    float sc0[DL], sc1[DL];
#pragma unroll
    for (int l = 0; l < DL; l++) {
        float delta = tstamp[(size_t)s * DL + l] - ts9;
        float a0 = 0.f, a1 = 0.f;
#pragma unroll
        for (int i = 0; i < 8; i++) {
            float te = __cosf(fmaf(delta, wt[i], bt[i]));
            a0 = fmaf(te, u0[i], a0);
            a1 = fmaf(te, u1[i], a1);
        }
#pragma unroll
        for (int o = 16; o; o >>= 1) {
            a0 += __shfl_xor_sync(0xFFFFFFFF, a0, o);
            a1 += __shfl_xor_sync(0xFFFFFFFF, a1, o);
        }
        sc0[l] = a0 * scale;
        sc1[l] = a1 * scale;
    }

    int pad = DL - (lengths[s] + 1);
    float mx0 = -3.4e38f, mx1 = -3.4e38f;
#pragma unroll
    for (int l = 0; l < DL; l++) {
        sc0[l] = (l < pad) ? -1e9f : sc0[l];
        sc1[l] = (l < pad) ? -1e9f : sc1[l];
        mx0 = fmaxf(mx0, sc0[l]);
        mx1 = fmaxf(mx1, sc1[l]);
    }
    float sm0 = 0.f, sm1 = 0.f;
#pragma unroll
    for (int l = 0; l < DL; l++) {
        sc0[l] = __expf(sc0[l] - mx0); sm0 += sc0[l];
        sc1[l] = __expf(sc1[l] - mx1); sm1 += sc1[l];
    }
    float i0 = 1.f / sm0, i1 = 1.f / sm1;
#pragma unroll
    for (int l = 0; l < DL; l++) { sc0[l] *= i0; sc1[l] *= i1; }

#pragma unroll
    for (int i = 0; i < 8; i++) {
        int e = lane + i * 32;
        float m0 = 0.f, m1 = 0.f;
        const float* mp = msgs + (size_t)s * DL * DD + e;
#pragma unroll
        for (int l = 0; l < DL; l++) {
            float v = __ldg(mp + l * DD);
            m0 = fmaf(sc0[l], v, m0);
            m1 = fmaf(sc1[l], v, m1);
        }
        __nv_bfloat16 h, lo;
        split_bf16(m0, h, lo);
        g_Mbh[(size_t)s * 512 + e] = h;  g_Mbl[(size_t)s * 512 + e] = lo;
        split_bf16(m1, h, lo);
        g_Mbh[(size_t)s * 512 + 256 + e] = h;  g_Mbl[(size_t)s * 512 + 256 + e] = lo;
    }
}

// ======================= launch =======================

extern "C" void kernel_launch(void* const* d_in, const int* in_sizes, int n_in,
                              void* d_out, int out_size) {
    const float* msgs    = (const float*)d_in[0];
    const float* ts      = (const float*)d_in[1];
    const float* w_time  = (const float*)d_in[2];
    const float* b_time  = (const float*)d_in[3];
    const float* w_in    = (const float*)d_in[4];
    const float* b_in    = (const float*)d_in[5];
    const float* w_out   = (const float*)d_in[6];
    const float* b_out   = (const float*)d_in[7];
    const int*   lengths = (const int*)d_in[8];
    float* out = (float*)d_out;

    cudaFuncSetAttribute(gemm1_k, cudaFuncAttributeMaxDynamicSharedMemorySize, GEMM_SMEM);
    cudaFuncSetAttribute(gemm2_k, cudaFuncAttributeMaxDynamicSharedMemorySize, GEMM_SMEM);

    prep<<<4483, 256>>>(w_in, b_in, w_out, b_out, msgs);
    gemm1_k<<<dim3(128, 4), 256, GEMM_SMEM>>>();
    score_agg<<<2048, 256>>>(msgs, ts, w_time, b_time, lengths);
    gemm2_k<<<dim3(128, 2), 256, GEMM_SMEM>>>(out);
}

// round 6
// speedup vs baseline: 3.9496x; 1.2203x over previous
#include <cuda_runtime.h>
#include <cuda_fp16.h>
#include <cstdint>
#include <math.h>

#define DN 16384
#define DL 10
#define DD 256

// ======================= helpers =======================

__device__ __forceinline__ uint32_t smem_u32(const void* p) {
    uint32_t a;
    asm("{ .reg .u64 t; cvta.to.shared.u64 t, %1; cvt.u32.u64 %0, t; }" : "=r"(a) : "l"(p));
    return a;
}

__device__ __forceinline__ void ldsm4(uint32_t* r, uint32_t a) {
    asm volatile("ldmatrix.sync.aligned.m8n8.x4.shared.b16 {%0,%1,%2,%3}, [%4];"
                 : "=r"(r[0]), "=r"(r[1]), "=r"(r[2]), "=r"(r[3]) : "r"(a));
}

__device__ __forceinline__ void mma16816(float* c, const uint32_t* a, uint32_t b0, uint32_t b1) {
    asm volatile("mma.sync.aligned.m16n8k16.row.col.f32.f16.f16.f32 "
                 "{%0,%1,%2,%3}, {%4,%5,%6,%7}, {%8,%9}, {%0,%1,%2,%3};"
                 : "+f"(c[0]), "+f"(c[1]), "+f"(c[2]), "+f"(c[3])
                 : "r"(a[0]), "r"(a[1]), "r"(a[2]), "r"(a[3]), "r"(b0), "r"(b1));
}

__device__ __forceinline__ void cp16(uint32_t s, const void* g) {
    asm volatile("cp.async.cg.shared.global [%0], [%1], 16;" :: "r"(s), "l"(g) : "memory");
}

__device__ __forceinline__ void split_f16(float x, __half& h, __half& l) {
    h = __float2half_rn(x);
    l = __float2half_rn(x - __half2float(h));
}

// ======================= globals (scratch) =======================

__device__ __align__(16) float g_r[2 * DD];
__device__ __align__(16) float g_bo[DD];

__device__ __align__(16) __half g_Gt_hi[2 * DD * DD];  // [512][256] (n-major, k contig)
__device__ __align__(16) __half g_Gt_lo[2 * DD * DD];
__device__ __align__(16) __half g_Wt_hi[DD * 2 * DD];  // [256][512]
__device__ __align__(16) __half g_Wt_lo[DD * 2 * DD];
__device__ __align__(16) __half g_M[(size_t)DN * DD];          // m_last fp16
__device__ __align__(16) float  g_U[(size_t)DN * 2 * DD];
__device__ __align__(16) __half g_Mb[(size_t)DN * 2 * DD];     // aggregated msgs fp16

// ======================= fused precompute =======================
// blocks [0,128):    G^T hi/lo   (each block: 4 k-rows of Gt[512][256])
// blocks [128,384):  W^T hi/lo   (each block: one d row of Wt[256][512])
// blocks [384,387):  bias folds g_r, g_bo
// blocks [387,4483): extract last message row -> fp16

__global__ void __launch_bounds__(256) prep(
    const float* __restrict__ w_in, const float* __restrict__ b_in,
    const float* __restrict__ w_out, const float* __restrict__ b_out,
    const float* __restrict__ msgs)
{
    __shared__ float sbuf[128 * 4];
    const int b = blockIdx.x;
    const int t = threadIdx.x;

    if (b < 128) {
        const int k0 = b * 4;
        const int h  = k0 >> 8;
        const int d0 = k0 & 255;
        {
            int j = t >> 1, half = t & 1;
            const float* wk = w_in + (size_t)(DD + h * 128 + j) * DD + d0 + half * 2;
            sbuf[j * 4 + half * 2]     = wk[0];
            sbuf[j * 4 + half * 2 + 1] = wk[1];
        }
        __syncthreads();
        const int e = t;
        float a0 = 0.f, a1 = 0.f, a2 = 0.f, a3 = 0.f;
        const float* wq = w_in + (size_t)(h * 128) * DD + e;
#pragma unroll 4
        for (int j = 0; j < 128; j++) {
            float q = wq[(size_t)j * DD];
            a0 = fmaf(q, sbuf[j * 4 + 0], a0);
            a1 = fmaf(q, sbuf[j * 4 + 1], a1);
            a2 = fmaf(q, sbuf[j * 4 + 2], a2);
            a3 = fmaf(q, sbuf[j * 4 + 3], a3);
        }
        float acc[4] = {a0, a1, a2, a3};
#pragma unroll
        for (int kk = 0; kk < 4; kk++) {
            __half hh, ll;
            split_f16(acc[kk], hh, ll);
            g_Gt_hi[(size_t)(k0 + kk) * DD + e] = hh;
            g_Gt_lo[(size_t)(k0 + kk) * DD + e] = ll;
        }
    } else if (b < 384) {
        const int d = b - 128;
        if (t < DD) sbuf[t] = w_out[(size_t)d * DD + t];
        __syncthreads();
#pragma unroll
        for (int rep = 0; rep < 2; rep++) {
            int k = t + rep * 256;
            int h = k >> 8, e = k & 255;
            const float* wv  = w_in + (size_t)(2 * DD + h * 128) * DD + e;
            const float* wor = sbuf + h * 128;
            float acc = 0.f;
#pragma unroll 8
            for (int j = 0; j < 128; j++)
                acc = fmaf(wor[j], wv[(size_t)j * DD], acc);
            __half hh, ll;
            split_f16(acc, hh, ll);
            g_Wt_hi[(size_t)d * 512 + k] = hh;
            g_Wt_lo[(size_t)d * 512 + k] = ll;
        }
    } else if (b < 387) {
        int sb = b - 384;
        if (sb < 2) {
            int h = sb, d = t;
            float a = 0.f;
            for (int j = 0; j < 128; j++)
                a = fmaf(w_in[(size_t)(DD + h * 128 + j) * DD + d], b_in[h * 128 + j], a);
            g_r[h * DD + d] = a;
        } else {
            float a = b_out[t];
            for (int c = 0; c < DD; c++)
                a = fmaf(w_out[(size_t)t * DD + c], b_in[2 * DD + c], a);
            g_bo[t] = a;
        }
    } else {
        int idx = (b - 387) * 256 + t;
        int n = idx >> 6, d4 = (idx & 63) * 4;
        float4 v = *reinterpret_cast<const float4*>(&msgs[((size_t)n * DL + (DL - 1)) * DD + d4]);
        __half2 p0 = __floats2half2_rn(v.x, v.y);
        __half2 p1 = __floats2half2_rn(v.z, v.w);
        *reinterpret_cast<__half2*>(&g_M[(size_t)n * DD + d4])     = p0;
        *reinterpret_cast<__half2*>(&g_M[(size_t)n * DD + d4 + 2]) = p1;
    }
}

// ======================= HMMA GEMM (3-stage cp.async, 2-pass fp16) =======================
// C[M,N] = A[M,KT] @ B[KT,N]; A fp16, B split hi/lo fp16 (BT[n][k]).
// CTA 128x128; 8 warps 2(m)x4(n); warp 64x32; K chunk 32, 3 stages.
// smem rows 80B (64B data + 16 pad) -> conflict-free ldmatrix.

#define SM_ROW 80
#define SM_BUF 10240             // 128*80
#define STAGE  (3 * SM_BUF)      // 30720 (A, Bh, Bl)
#define GEMM_SMEM (3 * STAGE)    // 92160

template<int KT>
__device__ __forceinline__ void gemm_body(
    const __half* __restrict__ A,
    const __half* __restrict__ Bh, const __half* __restrict__ Bl,
    const float* __restrict__ bias, float* __restrict__ C, int ldc)
{
    extern __shared__ char sm[];
    const int tid = threadIdx.x, lane = tid & 31, wid = tid >> 5;
    const int m0 = blockIdx.x * 128, n0 = blockIdx.y * 128;
    const int wm = (wid >> 2) * 64, wn = (wid & 3) * 32;
    const uint32_t sbase = smem_u32(sm);

    const int r0q = (tid + 0)   >> 2, q0 = tid & 3;
    const int r1q = (tid + 256) >> 2, q1 = tid & 3;

    float acc[4][4][4];
#pragma unroll
    for (int a = 0; a < 4; a++)
#pragma unroll
        for (int bq = 0; bq < 4; bq++)
#pragma unroll
            for (int cc = 0; cc < 4; cc++) acc[a][bq][cc] = 0.f;

#define LOAD_STAGE(st, k0c) do { \
        uint32_t s0 = sbase + (st) * STAGE; \
        { uint32_t so = (uint32_t)(r0q * SM_ROW + q0 * 16); \
          size_t ga = (size_t)(m0 + r0q) * KT + (k0c) + q0 * 8; \
          size_t gb = (size_t)(n0 + r0q) * KT + (k0c) + q0 * 8; \
          cp16(s0 + so, A + ga); \
          cp16(s0 + SM_BUF + so, Bh + gb); cp16(s0 + 2 * SM_BUF + so, Bl + gb); } \
        { uint32_t so = (uint32_t)(r1q * SM_ROW + q1 * 16); \
          size_t ga = (size_t)(m0 + r1q) * KT + (k0c) + q1 * 8; \
          size_t gb = (size_t)(n0 + r1q) * KT + (k0c) + q1 * 8; \
          cp16(s0 + so, A + ga); \
          cp16(s0 + SM_BUF + so, Bh + gb); cp16(s0 + 2 * SM_BUF + so, Bl + gb); } \
        asm volatile("cp.async.commit_group;" ::: "memory"); \
    } while (0)

    const int NC = KT / 32;
    LOAD_STAGE(0, 0);
    LOAD_STAGE(1, 32);
    int wr = 2;  // next stage slot to write
    for (int c = 0; c < NC; c++) {
        if (c + 2 < NC) {
            LOAD_STAGE(wr, (c + 2) * 32);
        } else {
            asm volatile("cp.async.commit_group;" ::: "memory");
        }
        wr = (wr + 1 == 3) ? 0 : wr + 1;
        asm volatile("cp.async.wait_group 2;" ::: "memory");
        __syncthreads();

        const int cur = c % 3;
        const uint32_t uA  = sbase + cur * STAGE;
        const uint32_t uBh = uA + SM_BUF;
        const uint32_t uBl = uA + 2 * SM_BUF;

#pragma unroll
        for (int kk = 0; kk < 2; kk++) {
            const uint32_t colb = (uint32_t)(kk * 32 + (lane >> 4) * 16);
            const uint32_t arow = (uint32_t)(wm + (lane & 15));
            uint32_t af[4][4], bh[2][4], bl[2][4];
#pragma unroll
            for (int mt = 0; mt < 4; mt++)
                ldsm4(af[mt], uA + (arow + mt * 16) * SM_ROW + colb);
#pragma unroll
            for (int nt = 0; nt < 2; nt++) {
                uint32_t brow = (uint32_t)(wn + nt * 16 + (lane & 15));
                ldsm4(bh[nt], uBh + brow * SM_ROW + colb);
                ldsm4(bl[nt], uBl + brow * SM_ROW + colb);
            }
#pragma unroll
            for (int mt = 0; mt < 4; mt++)
#pragma unroll
                for (int ns = 0; ns < 4; ns++) {
                    mma16816(acc[mt][ns], af[mt], bh[ns >> 1][ns & 1], bh[ns >> 1][(ns & 1) + 2]);
                    mma16816(acc[mt][ns], af[mt], bl[ns >> 1][ns & 1], bl[ns >> 1][(ns & 1) + 2]);
                }
        }
        __syncthreads();
    }
#undef LOAD_STAGE

    // epilogue: direct global stores + bias
#pragma unroll
    for (int mt = 0; mt < 4; mt++) {
        int r0 = m0 + wm + mt * 16 + (lane >> 2);
#pragma unroll
        for (int ns = 0; ns < 4; ns++) {
            int cx = n0 + wn + ns * 8 + (lane & 3) * 2;
            float2 bb = *reinterpret_cast<const float2*>(bias + cx);
            float2 v0, v1;
            v0.x = acc[mt][ns][0] + bb.x; v0.y = acc[mt][ns][1] + bb.y;
            v1.x = acc[mt][ns][2] + bb.x; v1.y = acc[mt][ns][3] + bb.y;
            *reinterpret_cast<float2*>(C + (size_t)r0 * ldc + cx) = v0;
            *reinterpret_cast<float2*>(C + (size_t)(r0 + 8) * ldc + cx) = v1;
        }
    }
}

__global__ void __launch_bounds__(256, 2) gemm1_k() {
    gemm_body<DD>(g_M, g_Gt_hi, g_Gt_lo, g_r, g_U, 2 * DD);
}
__global__ void __launch_bounds__(256, 2) gemm2_k(float* __restrict__ out) {
    gemm_body<2 * DD>(g_Mb, g_Wt_hi, g_Wt_lo, g_bo, out, DD);
}

// ======================= scores + softmax + aggregate =======================

__global__ void __launch_bounds__(256) score_agg(
    const float* __restrict__ msgs, const float* __restrict__ tstamp,
    const float* __restrict__ w_time, const float* __restrict__ b_time,
    const int* __restrict__ lengths)
{
    int wid = threadIdx.x >> 5, lane = threadIdx.x & 31;
    int s = blockIdx.x * 8 + wid;

    float wt[8], bt[8], u0[8], u1[8];
#pragma unroll
    for (int i = 0; i < 8; i++) {
        int d = lane + i * 32;
        wt[i] = w_time[d];
        bt[i] = b_time[d];
        u0[i] = g_U[(size_t)s * 512 + d];
        u1[i] = g_U[(size_t)s * 512 + 256 + d];
    }
    float ts9 = tstamp[(size_t)s * DL + (DL - 1)];
    const float scale = 0.08838834764831845f;

    float sc0[DL], sc1[DL];
#pragma unroll
    for (int l = 0; l < DL; l++) {
        float delta = tstamp[(size_t)s * DL + l] - ts9;
        float a0 = 0.f, a1 = 0.f;
#pragma unroll
        for (int i = 0; i < 8; i++) {
            float te = __cosf(fmaf(delta, wt[i], bt[i]));
            a0 = fmaf(te, u0[i], a0);
            a1 = fmaf(te, u1[i], a1);
        }
#pragma unroll
        for (int o = 16; o; o >>= 1) {
            a0 += __shfl_xor_sync(0xFFFFFFFF, a0, o);
            a1 += __shfl_xor_sync(0xFFFFFFFF, a1, o);
        }
        sc0[l] = a0 * scale;
        sc1[l] = a1 * scale;
    }

    int pad = DL - (lengths[s] + 1);
    float mx0 = -3.4e38f, mx1 = -3.4e38f;
#pragma unroll
    for (int l = 0; l < DL; l++) {
        sc0[l] = (l < pad) ? -1e9f : sc0[l];
        sc1[l] = (l < pad) ? -1e9f : sc1[l];
        mx0 = fmaxf(mx0, sc0[l]);
        mx1 = fmaxf(mx1, sc1[l]);
    }
    float sm0 = 0.f, sm1 = 0.f;
#pragma unroll
    for (int l = 0; l < DL; l++) {
        sc0[l] = __expf(sc0[l] - mx0); sm0 += sc0[l];
        sc1[l] = __expf(sc1[l] - mx1); sm1 += sc1[l];
    }
    float i0 = 1.f / sm0, i1 = 1.f / sm1;
#pragma unroll
    for (int l = 0; l < DL; l++) { sc0[l] *= i0; sc1[l] *= i1; }

#pragma unroll
    for (int i = 0; i < 8; i++) {
        int e = lane + i * 32;
        float m0 = 0.f, m1 = 0.f;
        const float* mp = msgs + (size_t)s * DL * DD + e;
#pragma unroll
        for (int l = 0; l < DL; l++) {
            float v = __ldg(mp + l * DD);
            m0 = fmaf(sc0[l], v, m0);
            m1 = fmaf(sc1[l], v, m1);
        }
        g_Mb[(size_t)s * 512 + e]       = __float2half_rn(m0);
        g_Mb[(size_t)s * 512 + 256 + e] = __float2half_rn(m1);
    }
}

// ======================= launch =======================

extern "C" void kernel_launch(void* const* d_in, const int* in_sizes, int n_in,
                              void* d_out, int out_size) {
    const float* msgs    = (const float*)d_in[0];
    const float* ts      = (const float*)d_in[1];
    const float* w_time  = (const float*)d_in[2];
    const float* b_time  = (const float*)d_in[3];
    const float* w_in    = (const float*)d_in[4];
    const float* b_in    = (const float*)d_in[5];
    const float* w_out   = (const float*)d_in[6];
    const float* b_out   = (const float*)d_in[7];
    const int*   lengths = (const int*)d_in[8];
    float* out = (float*)d_out;

    cudaFuncSetAttribute(gemm1_k, cudaFuncAttributeMaxDynamicSharedMemorySize, GEMM_SMEM);
    cudaFuncSetAttribute(gemm2_k, cudaFuncAttributeMaxDynamicSharedMemorySize, GEMM_SMEM);

    prep<<<4483, 256>>>(w_in, b_in, w_out, b_out, msgs);
    gemm1_k<<<dim3(128, 4), 256, GEMM_SMEM>>>();
    score_agg<<<2048, 256>>>(msgs, ts, w_time, b_time, lengths);
    gemm2_k<<<dim3(128, 2), 256, GEMM_SMEM>>>(out);
}

// round 7
// speedup vs baseline: 4.9016x; 1.2410x over previous
#include <cuda_runtime.h>
#include <cuda_fp16.h>
#include <cstdint>
#include <math.h>

#define DN 16384
#define DL 10
#define DD 256

// ======================= helpers =======================

__device__ __forceinline__ uint32_t smem_u32(const void* p) {
    uint32_t a;
    asm("{ .reg .u64 t; cvta.to.shared.u64 t, %1; cvt.u32.u64 %0, t; }" : "=r"(a) : "l"(p));
    return a;
}

__device__ __forceinline__ void ldsm4(uint32_t* r, uint32_t a) {
    asm volatile("ldmatrix.sync.aligned.m8n8.x4.shared.b16 {%0,%1,%2,%3}, [%4];"
                 : "=r"(r[0]), "=r"(r[1]), "=r"(r[2]), "=r"(r[3]) : "r"(a));
}

__device__ __forceinline__ void mma16816(float* c, const uint32_t* a, uint32_t b0, uint32_t b1) {
    asm volatile("mma.sync.aligned.m16n8k16.row.col.f32.f16.f16.f32 "
                 "{%0,%1,%2,%3}, {%4,%5,%6,%7}, {%8,%9}, {%0,%1,%2,%3};"
                 : "+f"(c[0]), "+f"(c[1]), "+f"(c[2]), "+f"(c[3])
                 : "r"(a[0]), "r"(a[1]), "r"(a[2]), "r"(a[3]), "r"(b0), "r"(b1));
}

__device__ __forceinline__ void cp16(uint32_t s, const void* g) {
    asm volatile("cp.async.cg.shared.global [%0], [%1], 16;" :: "r"(s), "l"(g) : "memory");
}

// ======================= globals (scratch) =======================

__device__ __align__(16) float g_r[2 * DD];
__device__ __align__(16) float g_bo[DD];

__device__ __align__(16) __half g_Gt[2 * DD * DD];   // [512][256] (n-major, k contig)
__device__ __align__(16) __half g_Wt[DD * 2 * DD];   // [256][512]
__device__ __align__(16) __half g_M[(size_t)DN * DD];        // m_last fp16
__device__ __align__(16) float  g_U[(size_t)DN * 2 * DD];
__device__ __align__(16) __half g_Mb[(size_t)DN * 2 * DD];   // aggregated msgs fp16

// ======================= fused precompute =======================
// blocks [0,128):    G^T  (each block: 4 k-rows of Gt[512][256])
// blocks [128,384):  W^T  (each block: one d row of Wt[256][512])
// blocks [384,387):  bias folds g_r, g_bo
// blocks [387,4483): extract last message row -> fp16

__global__ void __launch_bounds__(256) prep(
    const float* __restrict__ w_in, const float* __restrict__ b_in,
    const float* __restrict__ w_out, const float* __restrict__ b_out,
    const float* __restrict__ msgs)
{
    __shared__ float sbuf[128 * 4];
    const int b = blockIdx.x;
    const int t = threadIdx.x;

    if (b < 128) {
        const int k0 = b * 4;
        const int h  = k0 >> 8;
        const int d0 = k0 & 255;
        {
            int j = t >> 1, half = t & 1;
            const float* wk = w_in + (size_t)(DD + h * 128 + j) * DD + d0 + half * 2;
            sbuf[j * 4 + half * 2]     = wk[0];
            sbuf[j * 4 + half * 2 + 1] = wk[1];
        }
        __syncthreads();
        const int e = t;
        float a0 = 0.f, a1 = 0.f, a2 = 0.f, a3 = 0.f;
        const float* wq = w_in + (size_t)(h * 128) * DD + e;
#pragma unroll 4
        for (int j = 0; j < 128; j++) {
            float q = wq[(size_t)j * DD];
            a0 = fmaf(q, sbuf[j * 4 + 0], a0);
            a1 = fmaf(q, sbuf[j * 4 + 1], a1);
            a2 = fmaf(q, sbuf[j * 4 + 2], a2);
            a3 = fmaf(q, sbuf[j * 4 + 3], a3);
        }
        g_Gt[(size_t)(k0 + 0) * DD + e] = __float2half_rn(a0);
        g_Gt[(size_t)(k0 + 1) * DD + e] = __float2half_rn(a1);
        g_Gt[(size_t)(k0 + 2) * DD + e] = __float2half_rn(a2);
        g_Gt[(size_t)(k0 + 3) * DD + e] = __float2half_rn(a3);
    } else if (b < 384) {
        const int d = b - 128;
        if (t < DD) sbuf[t] = w_out[(size_t)d * DD + t];
        __syncthreads();
#pragma unroll
        for (int rep = 0; rep < 2; rep++) {
            int k = t + rep * 256;
            int h = k >> 8, e = k & 255;
            const float* wv  = w_in + (size_t)(2 * DD + h * 128) * DD + e;
            const float* wor = sbuf + h * 128;
            float acc = 0.f;
#pragma unroll 8
            for (int j = 0; j < 128; j++)
                acc = fmaf(wor[j], wv[(size_t)j * DD], acc);
            g_Wt[(size_t)d * 512 + k] = __float2half_rn(acc);
        }
    } else if (b < 387) {
        int sb = b - 384;
        if (sb < 2) {
            int h = sb, d = t;
            float a = 0.f;
            for (int j = 0; j < 128; j++)
                a = fmaf(w_in[(size_t)(DD + h * 128 + j) * DD + d], b_in[h * 128 + j], a);
            g_r[h * DD + d] = a;
        } else {
            float a = b_out[t];
            for (int c = 0; c < DD; c++)
                a = fmaf(w_out[(size_t)t * DD + c], b_in[2 * DD + c], a);
            g_bo[t] = a;
        }
    } else {
        int idx = (b - 387) * 256 + t;
        int n = idx >> 6, d4 = (idx & 63) * 4;
        float4 v = *reinterpret_cast<const float4*>(&msgs[((size_t)n * DL + (DL - 1)) * DD + d4]);
        __half2 p0 = __floats2half2_rn(v.x, v.y);
        __half2 p1 = __floats2half2_rn(v.z, v.w);
        *reinterpret_cast<__half2*>(&g_M[(size_t)n * DD + d4])     = p0;
        *reinterpret_cast<__half2*>(&g_M[(size_t)n * DD + d4 + 2]) = p1;
    }
}

// ======================= HMMA GEMM (3-stage cp.async, 1-pass fp16) =======================
// C[M,N] = A[M,KT] @ B[KT,N]; fp16 operands, fp32 accum; B transposed: BT[n][k].
// CTA 128x128; 8 warps 2(m)x4(n); warp 64x32; K chunk 64, 3 stages, 1 barrier/chunk.
// smem rows 144B (128B data + 16 pad) -> conflict-free ldmatrix.

#define SM_ROW 144
#define SM_BUF 18432             // 128*144
#define STAGE  (2 * SM_BUF)      // 36864 (A, B)
#define GEMM_SMEM (3 * STAGE)    // 110592

template<int KT>
__device__ __forceinline__ void gemm_body(
    const __half* __restrict__ A, const __half* __restrict__ B,
    const float* __restrict__ bias, float* __restrict__ C, int ldc)
{
    extern __shared__ char sm[];
    const int tid = threadIdx.x, lane = tid & 31, wid = tid >> 5;
    const int m0 = blockIdx.x * 128, n0 = blockIdx.y * 128;
    const int wm = (wid >> 2) * 64, wn = (wid & 3) * 32;
    const uint32_t sbase = smem_u32(sm);

    float acc[4][4][4];
#pragma unroll
    for (int a = 0; a < 4; a++)
#pragma unroll
        for (int bq = 0; bq < 4; bq++)
#pragma unroll
            for (int cc = 0; cc < 4; cc++) acc[a][bq][cc] = 0.f;

    // loader: 1024 16B txns per buffer; 4 iters x 256 threads
#define LOAD_STAGE(st, k0c) do { \
        uint32_t s0 = sbase + (st) * STAGE; \
        _Pragma("unroll") \
        for (int it = 0; it < 4; it++) { \
            int idx = tid + it * 256; \
            int r = idx >> 3, q = idx & 7; \
            uint32_t so = (uint32_t)(r * SM_ROW + q * 16); \
            size_t ga = (size_t)(m0 + r) * KT + (k0c) + q * 8; \
            size_t gb = (size_t)(n0 + r) * KT + (k0c) + q * 8; \
            cp16(s0 + so, A + ga); \
            cp16(s0 + SM_BUF + so, B + gb); \
        } \
        asm volatile("cp.async.commit_group;" ::: "memory"); \
    } while (0)

    const int NC = KT / 64;
    LOAD_STAGE(0, 0);
    LOAD_STAGE(1, 64);
    for (int c = 0; c < NC; c++) {
        asm volatile("cp.async.wait_group 1;" ::: "memory");
        __syncthreads();
        if (c + 2 < NC) {
            LOAD_STAGE((c + 2) % 3, (c + 2) * 64);
        } else {
            asm volatile("cp.async.commit_group;" ::: "memory");
        }

        const uint32_t uA = sbase + (c % 3) * STAGE;
        const uint32_t uB = uA + SM_BUF;

#pragma unroll
        for (int kk = 0; kk < 4; kk++) {
            const uint32_t colb = (uint32_t)(kk * 32 + (lane >> 4) * 16);
            const uint32_t arow = (uint32_t)(wm + (lane & 15));
            uint32_t af[4][4], bf[2][4];
#pragma unroll
            for (int mt = 0; mt < 4; mt++)
                ldsm4(af[mt], uA + (arow + mt * 16) * SM_ROW + colb);
#pragma unroll
            for (int nt = 0; nt < 2; nt++) {
                uint32_t brow = (uint32_t)(wn + nt * 16 + (lane & 15));
                ldsm4(bf[nt], uB + brow * SM_ROW + colb);
            }
#pragma unroll
            for (int mt = 0; mt < 4; mt++)
#pragma unroll
                for (int ns = 0; ns < 4; ns++)
                    mma16816(acc[mt][ns], af[mt], bf[ns >> 1][ns & 1], bf[ns >> 1][(ns & 1) + 2]);
        }
    }
#undef LOAD_STAGE

    // epilogue: direct global stores + bias
#pragma unroll
    for (int mt = 0; mt < 4; mt++) {
        int r0 = m0 + wm + mt * 16 + (lane >> 2);
#pragma unroll
        for (int ns = 0; ns < 4; ns++) {
            int cx = n0 + wn + ns * 8 + (lane & 3) * 2;
            float2 bb = *reinterpret_cast<const float2*>(bias + cx);
            float2 v0, v1;
            v0.x = acc[mt][ns][0] + bb.x; v0.y = acc[mt][ns][1] + bb.y;
            v1.x = acc[mt][ns][2] + bb.x; v1.y = acc[mt][ns][3] + bb.y;
            *reinterpret_cast<float2*>(C + (size_t)r0 * ldc + cx) = v0;
            *reinterpret_cast<float2*>(C + (size_t)(r0 + 8) * ldc + cx) = v1;
        }
    }
}

__global__ void __launch_bounds__(256, 2) gemm1_k() {
    gemm_body<DD>(g_M, g_Gt, g_r, g_U, 2 * DD);
}
__global__ void __launch_bounds__(256, 2) gemm2_k(float* __restrict__ out) {
    gemm_body<2 * DD>(g_Mb, g_Wt, g_bo, out, DD);
}

// ======================= scores + softmax + aggregate =======================

__global__ void __launch_bounds__(256) score_agg(
    const float* __restrict__ msgs, const float* __restrict__ tstamp,
    const float* __restrict__ w_time, const float* __restrict__ b_time,
    const int* __restrict__ lengths)
{
    int wid = threadIdx.x >> 5, lane = threadIdx.x & 31;
    int s = blockIdx.x * 8 + wid;

    float4 wt[2], bt[2], u0[2], u1[2];
#pragma unroll
    for (int i = 0; i < 2; i++) {
        int d4 = lane * 4 + i * 128;
        wt[i] = *reinterpret_cast<const float4*>(w_time + d4);
        bt[i] = *reinterpret_cast<const float4*>(b_time + d4);
        u0[i] = *reinterpret_cast<const float4*>(&g_U[(size_t)s * 512 + d4]);
        u1[i] = *reinterpret_cast<const float4*>(&g_U[(size_t)s * 512 + 256 + d4]);
    }
    float ts9 = tstamp[(size_t)s * DL + (DL - 1)];
    const float scale = 0.08838834764831845f;

    float sc0[DL], sc1[DL];
#pragma unroll
    for (int l = 0; l < DL; l++) {
        float delta = tstamp[(size_t)s * DL + l] - ts9;
        float a0 = 0.f, a1 = 0.f;
#pragma unroll
        for (int i = 0; i < 2; i++) {
            const float* w = reinterpret_cast<const float*>(&wt[i]);
            const float* b = reinterpret_cast<const float*>(&bt[i]);
            const float* p0 = reinterpret_cast<const float*>(&u0[i]);
            const float* p1 = reinterpret_cast<const float*>(&u1[i]);
#pragma unroll
            for (int j = 0; j < 4; j++) {
                float te = __cosf(fmaf(delta, w[j], b[j]));
                a0 = fmaf(te, p0[j], a0);
                a1 = fmaf(te, p1[j], a1);
            }
        }
#pragma unroll
        for (int o = 16; o; o >>= 1) {
            a0 += __shfl_xor_sync(0xFFFFFFFF, a0, o);
            a1 += __shfl_xor_sync(0xFFFFFFFF, a1, o);
        }
        sc0[l] = a0 * scale;
        sc1[l] = a1 * scale;
    }

    int pad = DL - (lengths[s] + 1);
    float mx0 = -3.4e38f, mx1 = -3.4e38f;
#pragma unroll
    for (int l = 0; l < DL; l++) {
        sc0[l] = (l < pad) ? -1e9f : sc0[l];
        sc1[l] = (l < pad) ? -1e9f : sc1[l];
        mx0 = fmaxf(mx0, sc0[l]);
        mx1 = fmaxf(mx1, sc1[l]);
    }
    float sm0 = 0.f, sm1 = 0.f;
#pragma unroll
    for (int l = 0; l < DL; l++) {
        sc0[l] = __expf(sc0[l] - mx0); sm0 += sc0[l];
        sc1[l] = __expf(sc1[l] - mx1); sm1 += sc1[l];
    }
    float i0 = 1.f / sm0, i1 = 1.f / sm1;
#pragma unroll
    for (int l = 0; l < DL; l++) { sc0[l] *= i0; sc1[l] *= i1; }

    // aggregate with float4 loads
#pragma unroll
    for (int i = 0; i < 2; i++) {
        int e4 = lane * 4 + i * 128;
        float m0[4] = {0.f, 0.f, 0.f, 0.f};
        float m1[4] = {0.f, 0.f, 0.f, 0.f};
        const float* mp = msgs + (size_t)s * DL * DD + e4;
#pragma unroll
        for (int l = 0; l < DL; l++) {
            float4 v = *reinterpret_cast<const float4*>(mp + (size_t)l * DD);
            m0[0] = fmaf(sc0[l], v.x, m0[0]); m0[1] = fmaf(sc0[l], v.y, m0[1]);
            m0[2] = fmaf(sc0[l], v.z, m0[2]); m0[3] = fmaf(sc0[l], v.w, m0[3]);
            m1[0] = fmaf(sc1[l], v.x, m1[0]); m1[1] = fmaf(sc1[l], v.y, m1[1]);
            m1[2] = fmaf(sc1[l], v.z, m1[2]); m1[3] = fmaf(sc1[l], v.w, m1[3]);
        }
        __half2 h00 = __floats2half2_rn(m0[0], m0[1]);
        __half2 h01 = __floats2half2_rn(m0[2], m0[3]);
        __half2 h10 = __floats2half2_rn(m1[0], m1[1]);
        __half2 h11 = __floats2half2_rn(m1[2], m1[3]);
        *reinterpret_cast<__half2*>(&g_Mb[(size_t)s * 512 + e4])           = h00;
        *reinterpret_cast<__half2*>(&g_Mb[(size_t)s * 512 + e4 + 2])       = h01;
        *reinterpret_cast<__half2*>(&g_Mb[(size_t)s * 512 + 256 + e4])     = h10;
        *reinterpret_cast<__half2*>(&g_Mb[(size_t)s * 512 + 256 + e4 + 2]) = h11;
    }
}

// ======================= launch =======================

extern "C" void kernel_launch(void* const* d_in, const int* in_sizes, int n_in,
                              void* d_out, int out_size) {
    const float* msgs    = (const float*)d_in[0];
    const float* ts      = (const float*)d_in[1];
    const float* w_time  = (const float*)d_in[2];
    const float* b_time  = (const float*)d_in[3];
    const float* w_in    = (const float*)d_in[4];
    const float* b_in    = (const float*)d_in[5];
    const float* w_out   = (const float*)d_in[6];
    const float* b_out   = (const float*)d_in[7];
    const int*   lengths = (const int*)d_in[8];
    float* out = (float*)d_out;

    cudaFuncSetAttribute(gemm1_k, cudaFuncAttributeMaxDynamicSharedMemorySize, GEMM_SMEM);
    cudaFuncSetAttribute(gemm2_k, cudaFuncAttributeMaxDynamicSharedMemorySize, GEMM_SMEM);

    prep<<<4483, 256>>>(w_in, b_in, w_out, b_out, msgs);
    gemm1_k<<<dim3(128, 4), 256, GEMM_SMEM>>>();
    score_agg<<<2048, 256>>>(msgs, ts, w_time, b_time, lengths);
    gemm2_k<<<dim3(128, 2), 256, GEMM_SMEM>>>(out);
}

// round 8
// speedup vs baseline: 5.2808x; 1.0774x over previous
#include <cuda_runtime.h>
#include <cuda_fp16.h>
#include <cstdint>
#include <math.h>

#define DN 16384
#define DL 10
#define DD 256

// ======================= helpers =======================

__device__ __forceinline__ uint32_t smem_u32(const void* p) {
    uint32_t a;
    asm("{ .reg .u64 t; cvta.to.shared.u64 t, %1; cvt.u32.u64 %0, t; }" : "=r"(a) : "l"(p));
    return a;
}

__device__ __forceinline__ void ldsm4(uint32_t* r, uint32_t a) {
    asm volatile("ldmatrix.sync.aligned.m8n8.x4.shared.b16 {%0,%1,%2,%3}, [%4];"
                 : "=r"(r[0]), "=r"(r[1]), "=r"(r[2]), "=r"(r[3]) : "r"(a));
}

__device__ __forceinline__ void mma16816(float* c, const uint32_t* a, uint32_t b0, uint32_t b1) {
    asm volatile("mma.sync.aligned.m16n8k16.row.col.f32.f16.f16.f32 "
                 "{%0,%1,%2,%3}, {%4,%5,%6,%7}, {%8,%9}, {%0,%1,%2,%3};"
                 : "+f"(c[0]), "+f"(c[1]), "+f"(c[2]), "+f"(c[3])
                 : "r"(a[0]), "r"(a[1]), "r"(a[2]), "r"(a[3]), "r"(b0), "r"(b1));
}

__device__ __forceinline__ void cp16(uint32_t s, const void* g) {
    asm volatile("cp.async.cg.shared.global [%0], [%1], 16;" :: "r"(s), "l"(g) : "memory");
}

// ======================= globals (scratch) =======================

__device__ __align__(16) float g_r[2 * DD];
__device__ __align__(16) float g_bo[DD];

__device__ __align__(16) __half g_Gt[2 * DD * DD];   // [512][256] (n-major, k contig)
__device__ __align__(16) __half g_Wt[DD * 2 * DD];   // [256][512]
__device__ __align__(16) __half g_M[(size_t)DN * DD];        // m_last fp16
__device__ __align__(16) __half g_U[(size_t)DN * 2 * DD];    // U fp16
__device__ __align__(16) __half g_Mb[(size_t)DN * 2 * DD];   // aggregated msgs fp16

// ======================= fused precompute =======================

__global__ void __launch_bounds__(256) prep(
    const float* __restrict__ w_in, const float* __restrict__ b_in,
    const float* __restrict__ w_out, const float* __restrict__ b_out,
    const float* __restrict__ msgs)
{
    __shared__ float sbuf[128 * 4];
    const int b = blockIdx.x;
    const int t = threadIdx.x;

    if (b < 128) {
        const int k0 = b * 4;
        const int h  = k0 >> 8;
        const int d0 = k0 & 255;
        {
            int j = t >> 1, half = t & 1;
            const float* wk = w_in + (size_t)(DD + h * 128 + j) * DD + d0 + half * 2;
            sbuf[j * 4 + half * 2]     = wk[0];
            sbuf[j * 4 + half * 2 + 1] = wk[1];
        }
        __syncthreads();
        const int e = t;
        float a0 = 0.f, a1 = 0.f, a2 = 0.f, a3 = 0.f;
        const float* wq = w_in + (size_t)(h * 128) * DD + e;
#pragma unroll 4
        for (int j = 0; j < 128; j++) {
            float q = wq[(size_t)j * DD];
            a0 = fmaf(q, sbuf[j * 4 + 0], a0);
            a1 = fmaf(q, sbuf[j * 4 + 1], a1);
            a2 = fmaf(q, sbuf[j * 4 + 2], a2);
            a3 = fmaf(q, sbuf[j * 4 + 3], a3);
        }
        g_Gt[(size_t)(k0 + 0) * DD + e] = __float2half_rn(a0);
        g_Gt[(size_t)(k0 + 1) * DD + e] = __float2half_rn(a1);
        g_Gt[(size_t)(k0 + 2) * DD + e] = __float2half_rn(a2);
        g_Gt[(size_t)(k0 + 3) * DD + e] = __float2half_rn(a3);
    } else if (b < 384) {
        const int d = b - 128;
        if (t < DD) sbuf[t] = w_out[(size_t)d * DD + t];
        __syncthreads();
#pragma unroll
        for (int rep = 0; rep < 2; rep++) {
            int k = t + rep * 256;
            int h = k >> 8, e = k & 255;
            const float* wv  = w_in + (size_t)(2 * DD + h * 128) * DD + e;
            const float* wor = sbuf + h * 128;
            float acc = 0.f;
#pragma unroll 8
            for (int j = 0; j < 128; j++)
                acc = fmaf(wor[j], wv[(size_t)j * DD], acc);
            g_Wt[(size_t)d * 512 + k] = __float2half_rn(acc);
        }
    } else if (b < 387) {
        int sb = b - 384;
        if (sb < 2) {
            int h = sb, d = t;
            float a = 0.f;
            for (int j = 0; j < 128; j++)
                a = fmaf(w_in[(size_t)(DD + h * 128 + j) * DD + d], b_in[h * 128 + j], a);
            g_r[h * DD + d] = a;
        } else {
            float a = b_out[t];
            for (int c = 0; c < DD; c++)
                a = fmaf(w_out[(size_t)t * DD + c], b_in[2 * DD + c], a);
            g_bo[t] = a;
        }
    } else {
        int idx = (b - 387) * 256 + t;
        int n = idx >> 6, d4 = (idx & 63) * 4;
        float4 v = *reinterpret_cast<const float4*>(&msgs[((size_t)n * DL + (DL - 1)) * DD + d4]);
        __half2 p0 = __floats2half2_rn(v.x, v.y);
        __half2 p1 = __floats2half2_rn(v.z, v.w);
        *reinterpret_cast<__half2*>(&g_M[(size_t)n * DD + d4])     = p0;
        *reinterpret_cast<__half2*>(&g_M[(size_t)n * DD + d4 + 2]) = p1;
    }
}

// ======================= HMMA GEMM (3-stage cp.async, interleaved loads) =======================
// C[M,N] = A[M,KT] @ B[KT,N]; fp16 operands, fp32 accum; B transposed: BT[n][k].
// CTA 128x128; 8 warps 2(m)x4(n); warp 64x32; K chunk 64, 3 stages, 1 barrier/chunk.
// Next-stage cp.asyncs spread across the 4 kk steps.

#define SM_ROW 144
#define SM_BUF 18432             // 128*144
#define STAGE  (2 * SM_BUF)      // 36864 (A, B)
#define GEMM_SMEM (3 * STAGE)    // 110592

template<int KT, bool HALF_OUT>
__device__ __forceinline__ void gemm_body(
    const __half* __restrict__ A, const __half* __restrict__ B,
    const float* __restrict__ bias, void* __restrict__ Cv, int ldc)
{
    extern __shared__ char sm[];
    const int tid = threadIdx.x, lane = tid & 31, wid = tid >> 5;
    const int m0 = blockIdx.x * 128, n0 = blockIdx.y * 128;
    const int wm = (wid >> 2) * 64, wn = (wid & 3) * 32;
    const uint32_t sbase = smem_u32(sm);

    float acc[4][4][4];
#pragma unroll
    for (int a = 0; a < 4; a++)
#pragma unroll
        for (int bq = 0; bq < 4; bq++)
#pragma unroll
            for (int cc = 0; cc < 4; cc++) acc[a][bq][cc] = 0.f;

    // one load iteration: 32 rows of A + 32 rows of B (per `it` in 0..3)
#define LOAD_ITER(st, k0c, it) do { \
        uint32_t s0 = sbase + (st) * STAGE; \
        int idx = tid + (it) * 256; \
        int r = idx >> 3, q = idx & 7; \
        uint32_t so = (uint32_t)(r * SM_ROW + q * 16); \
        size_t ga = (size_t)(m0 + r) * KT + (k0c) + q * 8; \
        size_t gb = (size_t)(n0 + r) * KT + (k0c) + q * 8; \
        cp16(s0 + so, A + ga); \
        cp16(s0 + SM_BUF + so, B + gb); \
    } while (0)

#define LOAD_STAGE(st, k0c) do { \
        LOAD_ITER(st, k0c, 0); LOAD_ITER(st, k0c, 1); \
        LOAD_ITER(st, k0c, 2); LOAD_ITER(st, k0c, 3); \
        asm volatile("cp.async.commit_group;" ::: "memory"); \
    } while (0)

    const int NC = KT / 64;
    LOAD_STAGE(0, 0);
    LOAD_STAGE(1, 64);
    for (int c = 0; c < NC; c++) {
        asm volatile("cp.async.wait_group 1;" ::: "memory");
        __syncthreads();

        const uint32_t uA = sbase + (c % 3) * STAGE;
        const uint32_t uB = uA + SM_BUF;
        const bool do_load = (c + 2 < NC);
        const int  nst = (c + 2) % 3;
        const int  nk0 = (c + 2) * 64;

#pragma unroll
        for (int kk = 0; kk < 4; kk++) {
            const uint32_t colb = (uint32_t)(kk * 32 + (lane >> 4) * 16);
            const uint32_t arow = (uint32_t)(wm + (lane & 15));
            uint32_t af[4][4], bf[2][4];
#pragma unroll
            for (int nt = 0; nt < 2; nt++) {
                uint32_t brow = (uint32_t)(wn + nt * 16 + (lane & 15));
                ldsm4(bf[nt], uB + brow * SM_ROW + colb);
            }
#pragma unroll
            for (int mt = 0; mt < 4; mt++)
                ldsm4(af[mt], uA + (arow + mt * 16) * SM_ROW + colb);
            if (do_load) LOAD_ITER(nst, nk0, kk);
#pragma unroll
            for (int mt = 0; mt < 4; mt++)
#pragma unroll
                for (int ns = 0; ns < 4; ns++)
                    mma16816(acc[mt][ns], af[mt], bf[ns >> 1][ns & 1], bf[ns >> 1][(ns & 1) + 2]);
        }
        asm volatile("cp.async.commit_group;" ::: "memory");
    }
#undef LOAD_STAGE
#undef LOAD_ITER

    // epilogue: direct global stores + bias
#pragma unroll
    for (int mt = 0; mt < 4; mt++) {
        int r0 = m0 + wm + mt * 16 + (lane >> 2);
#pragma unroll
        for (int ns = 0; ns < 4; ns++) {
            int cx = n0 + wn + ns * 8 + (lane & 3) * 2;
            float2 bb = *reinterpret_cast<const float2*>(bias + cx);
            float x0 = acc[mt][ns][0] + bb.x, y0 = acc[mt][ns][1] + bb.y;
            float x1 = acc[mt][ns][2] + bb.x, y1 = acc[mt][ns][3] + bb.y;
            if (HALF_OUT) {
                __half* C = reinterpret_cast<__half*>(Cv);
                *reinterpret_cast<__half2*>(C + (size_t)r0 * ldc + cx)       = __floats2half2_rn(x0, y0);
                *reinterpret_cast<__half2*>(C + (size_t)(r0 + 8) * ldc + cx) = __floats2half2_rn(x1, y1);
            } else {
                float* C = reinterpret_cast<float*>(Cv);
                float2 v0; v0.x = x0; v0.y = y0;
                float2 v1; v1.x = x1; v1.y = y1;
                *reinterpret_cast<float2*>(C + (size_t)r0 * ldc + cx) = v0;
                *reinterpret_cast<float2*>(C + (size_t)(r0 + 8) * ldc + cx) = v1;
            }
        }
    }
}

__global__ void __launch_bounds__(256, 2) gemm1_k() {
    gemm_body<DD, true>(g_M, g_Gt, g_r, g_U, 2 * DD);
}
__global__ void __launch_bounds__(256, 2) gemm2_k(float* __restrict__ out) {
    gemm_body<2 * DD, false>(g_Mb, g_Wt, g_bo, out, DD);
}

// ======================= scores + softmax + aggregate =======================

__global__ void __launch_bounds__(256) score_agg(
    const float* __restrict__ msgs, const float* __restrict__ tstamp,
    const float* __restrict__ w_time, const float* __restrict__ b_time,
    const int* __restrict__ lengths)
{
    int wid = threadIdx.x >> 5, lane = threadIdx.x & 31;
    int s = blockIdx.x * 8 + wid;

    const int e8 = lane * 8;
    float wt[8], bt[8], u0[8], u1[8];
    {
        float4 wa = *reinterpret_cast<const float4*>(w_time + e8);
        float4 wb = *reinterpret_cast<const float4*>(w_time + e8 + 4);
        float4 ba = *reinterpret_cast<const float4*>(b_time + e8);
        float4 bb = *reinterpret_cast<const float4*>(b_time + e8 + 4);
        wt[0]=wa.x; wt[1]=wa.y; wt[2]=wa.z; wt[3]=wa.w;
        wt[4]=wb.x; wt[5]=wb.y; wt[6]=wb.z; wt[7]=wb.w;
        bt[0]=ba.x; bt[1]=ba.y; bt[2]=ba.z; bt[3]=ba.w;
        bt[4]=bb.x; bt[5]=bb.y; bt[6]=bb.z; bt[7]=bb.w;
        uint4 h0 = *reinterpret_cast<const uint4*>(&g_U[(size_t)s * 512 + e8]);
        uint4 h1 = *reinterpret_cast<const uint4*>(&g_U[(size_t)s * 512 + 256 + e8]);
        const __half2* p0 = reinterpret_cast<const __half2*>(&h0);
        const __half2* p1 = reinterpret_cast<const __half2*>(&h1);
#pragma unroll
        for (int j = 0; j < 4; j++) {
            float2 f0 = __half22float2(p0[j]);
            float2 f1 = __half22float2(p1[j]);
            u0[2*j] = f0.x; u0[2*j+1] = f0.y;
            u1[2*j] = f1.x; u1[2*j+1] = f1.y;
        }
    }
    float ts9 = tstamp[(size_t)s * DL + (DL - 1)];
    const float scale = 0.08838834764831845f;

    float sc0[DL], sc1[DL];
#pragma unroll
    for (int l = 0; l < DL; l++) {
        float delta = tstamp[(size_t)s * DL + l] - ts9;
        float a0 = 0.f, a1 = 0.f;
#pragma unroll
        for (int j = 0; j < 8; j++) {
            float te = __cosf(fmaf(delta, wt[j], bt[j]));
            a0 = fmaf(te, u0[j], a0);
            a1 = fmaf(te, u1[j], a1);
        }
#pragma unroll
        for (int o = 16; o; o >>= 1) {
            a0 += __shfl_xor_sync(0xFFFFFFFF, a0, o);
            a1 += __shfl_xor_sync(0xFFFFFFFF, a1, o);
        }
        sc0[l] = a0 * scale;
        sc1[l] = a1 * scale;
    }

    int pad = DL - (lengths[s] + 1);
    float mx0 = -3.4e38f, mx1 = -3.4e38f;
#pragma unroll
    for (int l = 0; l < DL; l++) {
        sc0[l] = (l < pad) ? -1e9f : sc0[l];
        sc1[l] = (l < pad) ? -1e9f : sc1[l];
        mx0 = fmaxf(mx0, sc0[l]);
        mx1 = fmaxf(mx1, sc1[l]);
    }
    float sm0 = 0.f, sm1 = 0.f;
#pragma unroll
    for (int l = 0; l < DL; l++) {
        sc0[l] = __expf(sc0[l] - mx0); sm0 += sc0[l];
        sc1[l] = __expf(sc1[l] - mx1); sm1 += sc1[l];
    }
    float i0 = 1.f / sm0, i1 = 1.f / sm1;
#pragma unroll
    for (int l = 0; l < DL; l++) { sc0[l] *= i0; sc1[l] *= i1; }

    // aggregate with float4 loads
#pragma unroll
    for (int i = 0; i < 2; i++) {
        int e4 = lane * 4 + i * 128;
        float m0[4] = {0.f, 0.f, 0.f, 0.f};
        float m1[4] = {0.f, 0.f, 0.f, 0.f};
        const float* mp = msgs + (size_t)s * DL * DD + e4;
#pragma unroll
        for (int l = 0; l < DL; l++) {
            float4 v = *reinterpret_cast<const float4*>(mp + (size_t)l * DD);
            m0[0] = fmaf(sc0[l], v.x, m0[0]); m0[1] = fmaf(sc0[l], v.y, m0[1]);
            m0[2] = fmaf(sc0[l], v.z, m0[2]); m0[3] = fmaf(sc0[l], v.w, m0[3]);
            m1[0] = fmaf(sc1[l], v.x, m1[0]); m1[1] = fmaf(sc1[l], v.y, m1[1]);
            m1[2] = fmaf(sc1[l], v.z, m1[2]); m1[3] = fmaf(sc1[l], v.w, m1[3]);
        }
        __half2 h00 = __floats2half2_rn(m0[0], m0[1]);
        __half2 h01 = __floats2half2_rn(m0[2], m0[3]);
        __half2 h10 = __floats2half2_rn(m1[0], m1[1]);
        __half2 h11 = __floats2half2_rn(m1[2], m1[3]);
        *reinterpret_cast<__half2*>(&g_Mb[(size_t)s * 512 + e4])           = h00;
        *reinterpret_cast<__half2*>(&g_Mb[(size_t)s * 512 + e4 + 2])       = h01;
        *reinterpret_cast<__half2*>(&g_Mb[(size_t)s * 512 + 256 + e4])     = h10;
        *reinterpret_cast<__half2*>(&g_Mb[(size_t)s * 512 + 256 + e4 + 2]) = h11;
    }
}

// ======================= launch =======================

extern "C" void kernel_launch(void* const* d_in, const int* in_sizes, int n_in,
                              void* d_out, int out_size) {
    const float* msgs    = (const float*)d_in[0];
    const float* ts      = (const float*)d_in[1];
    const float* w_time  = (const float*)d_in[2];
    const float* b_time  = (const float*)d_in[3];
    const float* w_in    = (const float*)d_in[4];
    const float* b_in    = (const float*)d_in[5];
    const float* w_out   = (const float*)d_in[6];
    const float* b_out   = (const float*)d_in[7];
    const int*   lengths = (const int*)d_in[8];
    float* out = (float*)d_out;

    cudaFuncSetAttribute(gemm1_k, cudaFuncAttributeMaxDynamicSharedMemorySize, GEMM_SMEM);
    cudaFuncSetAttribute(gemm2_k, cudaFuncAttributeMaxDynamicSharedMemorySize, GEMM_SMEM);

    prep<<<4483, 256>>>(w_in, b_in, w_out, b_out, msgs);
    gemm1_k<<<dim3(128, 4), 256, GEMM_SMEM>>>();
    score_agg<<<2048, 256>>>(msgs, ts, w_time, b_time, lengths);
    gemm2_k<<<dim3(128, 2), 256, GEMM_SMEM>>>(out);
}

// round 9
// speedup vs baseline: 5.5212x; 1.0455x over previous
#include <cuda_runtime.h>
#include <cuda_fp16.h>
#include <cstdint>
#include <math.h>

#define DN 16384
#define DL 10
#define DD 256

// ======================= helpers =======================

__device__ __forceinline__ uint32_t smem_u32(const void* p) {
    uint32_t a;
    asm("{ .reg .u64 t; cvta.to.shared.u64 t, %1; cvt.u32.u64 %0, t; }" : "=r"(a) : "l"(p));
    return a;
}

__device__ __forceinline__ void ldsm4(uint32_t* r, uint32_t a) {
    asm volatile("ldmatrix.sync.aligned.m8n8.x4.shared.b16 {%0,%1,%2,%3}, [%4];"
                 : "=r"(r[0]), "=r"(r[1]), "=r"(r[2]), "=r"(r[3]) : "r"(a));
}

__device__ __forceinline__ void mma16816(float* c, const uint32_t* a, uint32_t b0, uint32_t b1) {
    asm volatile("mma.sync.aligned.m16n8k16.row.col.f32.f16.f16.f32 "
                 "{%0,%1,%2,%3}, {%4,%5,%6,%7}, {%8,%9}, {%0,%1,%2,%3};"
                 : "+f"(c[0]), "+f"(c[1]), "+f"(c[2]), "+f"(c[3])
                 : "r"(a[0]), "r"(a[1]), "r"(a[2]), "r"(a[3]), "r"(b0), "r"(b1));
}

__device__ __forceinline__ void cp16(uint32_t s, const void* g) {
    asm volatile("cp.async.cg.shared.global [%0], [%1], 16;" :: "r"(s), "l"(g) : "memory");
}

// ======================= globals (scratch) =======================

__device__ __align__(16) float g_r[2 * DD];
__device__ __align__(16) float g_bo[DD];

__device__ __align__(16) __half g_Gt[2 * DD * DD];   // [512][256] (n-major, k contig)
__device__ __align__(16) __half g_Wt[DD * 2 * DD];   // [256][512]
__device__ __align__(16) __half g_M[(size_t)DN * DD];        // m_last fp16
__device__ __align__(16) __half g_U[(size_t)DN * 2 * DD];    // U fp16
__device__ __align__(16) __half g_Mb[(size_t)DN * 2 * DD];   // aggregated msgs fp16

// ======================= fused precompute =======================

__global__ void __launch_bounds__(256) prep(
    const float* __restrict__ w_in, const float* __restrict__ b_in,
    const float* __restrict__ w_out, const float* __restrict__ b_out,
    const float* __restrict__ msgs)
{
    __shared__ float sbuf[128 * 4];
    const int b = blockIdx.x;
    const int t = threadIdx.x;

    if (b < 128) {
        const int k0 = b * 4;
        const int h  = k0 >> 8;
        const int d0 = k0 & 255;
        {
            int j = t >> 1, half = t & 1;
            const float* wk = w_in + (size_t)(DD + h * 128 + j) * DD + d0 + half * 2;
            sbuf[j * 4 + half * 2]     = wk[0];
            sbuf[j * 4 + half * 2 + 1] = wk[1];
        }
        __syncthreads();
        const int e = t;
        float a0 = 0.f, a1 = 0.f, a2 = 0.f, a3 = 0.f;
        const float* wq = w_in + (size_t)(h * 128) * DD + e;
#pragma unroll 4
        for (int j = 0; j < 128; j++) {
            float q = wq[(size_t)j * DD];
            a0 = fmaf(q, sbuf[j * 4 + 0], a0);
            a1 = fmaf(q, sbuf[j * 4 + 1], a1);
            a2 = fmaf(q, sbuf[j * 4 + 2], a2);
            a3 = fmaf(q, sbuf[j * 4 + 3], a3);
        }
        g_Gt[(size_t)(k0 + 0) * DD + e] = __float2half_rn(a0);
        g_Gt[(size_t)(k0 + 1) * DD + e] = __float2half_rn(a1);
        g_Gt[(size_t)(k0 + 2) * DD + e] = __float2half_rn(a2);
        g_Gt[(size_t)(k0 + 3) * DD + e] = __float2half_rn(a3);
    } else if (b < 384) {
        const int d = b - 128;
        if (t < DD) sbuf[t] = w_out[(size_t)d * DD + t];
        __syncthreads();
#pragma unroll
        for (int rep = 0; rep < 2; rep++) {
            int k = t + rep * 256;
            int h = k >> 8, e = k & 255;
            const float* wv  = w_in + (size_t)(2 * DD + h * 128) * DD + e;
            const float* wor = sbuf + h * 128;
            float acc = 0.f;
#pragma unroll 8
            for (int j = 0; j < 128; j++)
                acc = fmaf(wor[j], wv[(size_t)j * DD], acc);
            g_Wt[(size_t)d * 512 + k] = __float2half_rn(acc);
        }
    } else if (b < 387) {
        int sb = b - 384;
        if (sb < 2) {
            int h = sb, d = t;
            float a = 0.f;
            for (int j = 0; j < 128; j++)
                a = fmaf(w_in[(size_t)(DD + h * 128 + j) * DD + d], b_in[h * 128 + j], a);
            g_r[h * DD + d] = a;
        } else {
            float a = b_out[t];
            for (int c = 0; c < DD; c++)
                a = fmaf(w_out[(size_t)t * DD + c], b_in[2 * DD + c], a);
            g_bo[t] = a;
        }
    } else {
        int idx = (b - 387) * 256 + t;
        int n = idx >> 6, d4 = (idx & 63) * 4;
        float4 v = *reinterpret_cast<const float4*>(&msgs[((size_t)n * DL + (DL - 1)) * DD + d4]);
        __half2 p0 = __floats2half2_rn(v.x, v.y);
        __half2 p1 = __floats2half2_rn(v.z, v.w);
        *reinterpret_cast<__half2*>(&g_M[(size_t)n * DD + d4])     = p0;
        *reinterpret_cast<__half2*>(&g_M[(size_t)n * DD + d4 + 2]) = p1;
    }
}

// ======================= HMMA GEMM (3-stage cp.async, interleaved loads) =======================

#define SM_ROW 144
#define SM_BUF 18432             // 128*144
#define STAGE  (2 * SM_BUF)      // 36864 (A, B)
#define GEMM_SMEM (3 * STAGE)    // 110592

template<int KT, bool HALF_OUT>
__device__ __forceinline__ void gemm_body(
    const __half* __restrict__ A, const __half* __restrict__ B,
    const float* __restrict__ bias, void* __restrict__ Cv, int ldc)
{
    extern __shared__ char sm[];
    const int tid = threadIdx.x, lane = tid & 31, wid = tid >> 5;
    const int m0 = blockIdx.x * 128, n0 = blockIdx.y * 128;
    const int wm = (wid >> 2) * 64, wn = (wid & 3) * 32;
    const uint32_t sbase = smem_u32(sm);

    float acc[4][4][4];
#pragma unroll
    for (int a = 0; a < 4; a++)
#pragma unroll
        for (int bq = 0; bq < 4; bq++)
#pragma unroll
            for (int cc = 0; cc < 4; cc++) acc[a][bq][cc] = 0.f;

#define LOAD_ITER(st, k0c, it) do { \
        uint32_t s0 = sbase + (st) * STAGE; \
        int idx = tid + (it) * 256; \
        int r = idx >> 3, q = idx & 7; \
        uint32_t so = (uint32_t)(r * SM_ROW + q * 16); \
        size_t ga = (size_t)(m0 + r) * KT + (k0c) + q * 8; \
        size_t gb = (size_t)(n0 + r) * KT + (k0c) + q * 8; \
        cp16(s0 + so, A + ga); \
        cp16(s0 + SM_BUF + so, B + gb); \
    } while (0)

#define LOAD_STAGE(st, k0c) do { \
        LOAD_ITER(st, k0c, 0); LOAD_ITER(st, k0c, 1); \
        LOAD_ITER(st, k0c, 2); LOAD_ITER(st, k0c, 3); \
        asm volatile("cp.async.commit_group;" ::: "memory"); \
    } while (0)

    const int NC = KT / 64;
    LOAD_STAGE(0, 0);
    LOAD_STAGE(1, 64);
    for (int c = 0; c < NC; c++) {
        asm volatile("cp.async.wait_group 1;" ::: "memory");
        __syncthreads();

        const uint32_t uA = sbase + (c % 3) * STAGE;
        const uint32_t uB = uA + SM_BUF;
        const bool do_load = (c + 2 < NC);
        const int  nst = (c + 2) % 3;
        const int  nk0 = (c + 2) * 64;

#pragma unroll
        for (int kk = 0; kk < 4; kk++) {
            const uint32_t colb = (uint32_t)(kk * 32 + (lane >> 4) * 16);
            const uint32_t arow = (uint32_t)(wm + (lane & 15));
            uint32_t af[4][4], bf[2][4];
#pragma unroll
            for (int nt = 0; nt < 2; nt++) {
                uint32_t brow = (uint32_t)(wn + nt * 16 + (lane & 15));
                ldsm4(bf[nt], uB + brow * SM_ROW + colb);
            }
#pragma unroll
            for (int mt = 0; mt < 4; mt++)
                ldsm4(af[mt], uA + (arow + mt * 16) * SM_ROW + colb);
            if (do_load) LOAD_ITER(nst, nk0, kk);
#pragma unroll
            for (int mt = 0; mt < 4; mt++)
#pragma unroll
                for (int ns = 0; ns < 4; ns++)
                    mma16816(acc[mt][ns], af[mt], bf[ns >> 1][ns & 1], bf[ns >> 1][(ns & 1) + 2]);
        }
        asm volatile("cp.async.commit_group;" ::: "memory");
    }
#undef LOAD_STAGE
#undef LOAD_ITER

#pragma unroll
    for (int mt = 0; mt < 4; mt++) {
        int r0 = m0 + wm + mt * 16 + (lane >> 2);
#pragma unroll
        for (int ns = 0; ns < 4; ns++) {
            int cx = n0 + wn + ns * 8 + (lane & 3) * 2;
            float2 bb = *reinterpret_cast<const float2*>(bias + cx);
            float x0 = acc[mt][ns][0] + bb.x, y0 = acc[mt][ns][1] + bb.y;
            float x1 = acc[mt][ns][2] + bb.x, y1 = acc[mt][ns][3] + bb.y;
            if (HALF_OUT) {
                __half* C = reinterpret_cast<__half*>(Cv);
                *reinterpret_cast<__half2*>(C + (size_t)r0 * ldc + cx)       = __floats2half2_rn(x0, y0);
                *reinterpret_cast<__half2*>(C + (size_t)(r0 + 8) * ldc + cx) = __floats2half2_rn(x1, y1);
            } else {
                float* C = reinterpret_cast<float*>(Cv);
                float2 v0; v0.x = x0; v0.y = y0;
                float2 v1; v1.x = x1; v1.y = y1;
                *reinterpret_cast<float2*>(C + (size_t)r0 * ldc + cx) = v0;
                *reinterpret_cast<float2*>(C + (size_t)(r0 + 8) * ldc + cx) = v1;
            }
        }
    }
}

__global__ void __launch_bounds__(256, 2) gemm1_k() {
    gemm_body<DD, true>(g_M, g_Gt, g_r, g_U, 2 * DD);
}
__global__ void __launch_bounds__(256, 2) gemm2_k(float* __restrict__ out) {
    gemm_body<2 * DD, false>(g_Mb, g_Wt, g_bo, out, DD);
}

// ======================= scores + softmax + aggregate (masked-row skip) =======================

__global__ void __launch_bounds__(256) score_agg(
    const float* __restrict__ msgs, const float* __restrict__ tstamp,
    const float* __restrict__ w_time, const float* __restrict__ b_time,
    const int* __restrict__ lengths)
{
    int wid = threadIdx.x >> 5, lane = threadIdx.x & 31;
    int s = blockIdx.x * 8 + wid;

    const int pad = DL - (lengths[s] + 1);   // rows l < pad have zero attention

    const int e8 = lane * 8;
    float wt[8], bt[8], u0[8], u1[8];
    {
        float4 wa = *reinterpret_cast<const float4*>(w_time + e8);
        float4 wb = *reinterpret_cast<const float4*>(w_time + e8 + 4);
        float4 ba = *reinterpret_cast<const float4*>(b_time + e8);
        float4 bb = *reinterpret_cast<const float4*>(b_time + e8 + 4);
        wt[0]=wa.x; wt[1]=wa.y; wt[2]=wa.z; wt[3]=wa.w;
        wt[4]=wb.x; wt[5]=wb.y; wt[6]=wb.z; wt[7]=wb.w;
        bt[0]=ba.x; bt[1]=ba.y; bt[2]=ba.z; bt[3]=ba.w;
        bt[4]=bb.x; bt[5]=bb.y; bt[6]=bb.z; bt[7]=bb.w;
        uint4 h0 = *reinterpret_cast<const uint4*>(&g_U[(size_t)s * 512 + e8]);
        uint4 h1 = *reinterpret_cast<const uint4*>(&g_U[(size_t)s * 512 + 256 + e8]);
        const __half2* p0 = reinterpret_cast<const __half2*>(&h0);
        const __half2* p1 = reinterpret_cast<const __half2*>(&h1);
#pragma unroll
        for (int j = 0; j < 4; j++) {
            float2 f0 = __half22float2(p0[j]);
            float2 f1 = __half22float2(p1[j]);
            u0[2*j] = f0.x; u0[2*j+1] = f0.y;
            u1[2*j] = f1.x; u1[2*j+1] = f1.y;
        }
    }
    float ts9 = tstamp[(size_t)s * DL + (DL - 1)];
    const float scale = 0.08838834764831845f;

    // scores only for valid rows (warp-uniform predicate)
    float sc0[DL], sc1[DL];
#pragma unroll
    for (int l = 0; l < DL; l++) {
        if (l >= pad) {
            float delta = tstamp[(size_t)s * DL + l] - ts9;
            float a0 = 0.f, a1 = 0.f;
#pragma unroll
            for (int j = 0; j < 8; j++) {
                float te = __cosf(fmaf(delta, wt[j], bt[j]));
                a0 = fmaf(te, u0[j], a0);
                a1 = fmaf(te, u1[j], a1);
            }
#pragma unroll
            for (int o = 16; o; o >>= 1) {
                a0 += __shfl_xor_sync(0xFFFFFFFF, a0, o);
                a1 += __shfl_xor_sync(0xFFFFFFFF, a1, o);
            }
            sc0[l] = a0 * scale;
            sc1[l] = a1 * scale;
        } else {
            sc0[l] = 0.f;
            sc1[l] = 0.f;
        }
    }

    float mx0 = -3.4e38f, mx1 = -3.4e38f;
#pragma unroll
    for (int l = 0; l < DL; l++) {
        if (l >= pad) {
            mx0 = fmaxf(mx0, sc0[l]);
            mx1 = fmaxf(mx1, sc1[l]);
        }
    }
    float sm0 = 0.f, sm1 = 0.f;
#pragma unroll
    for (int l = 0; l < DL; l++) {
        if (l >= pad) {
            sc0[l] = __expf(sc0[l] - mx0); sm0 += sc0[l];
            sc1[l] = __expf(sc1[l] - mx1); sm1 += sc1[l];
        }
    }
    float i0 = 1.f / sm0, i1 = 1.f / sm1;
#pragma unroll
    for (int l = 0; l < DL; l++) {
        if (l >= pad) { sc0[l] *= i0; sc1[l] *= i1; }
    }

    // aggregate: only valid rows generate loads
#pragma unroll
    for (int i = 0; i < 2; i++) {
        int e4 = lane * 4 + i * 128;
        float m0[4] = {0.f, 0.f, 0.f, 0.f};
        float m1[4] = {0.f, 0.f, 0.f, 0.f};
        const float* mp = msgs + (size_t)s * DL * DD + e4;
#pragma unroll
        for (int l = 0; l < DL; l++) {
            if (l >= pad) {
                float4 v = *reinterpret_cast<const float4*>(mp + (size_t)l * DD);
                m0[0] = fmaf(sc0[l], v.x, m0[0]); m0[1] = fmaf(sc0[l], v.y, m0[1]);
                m0[2] = fmaf(sc0[l], v.z, m0[2]); m0[3] = fmaf(sc0[l], v.w, m0[3]);
                m1[0] = fmaf(sc1[l], v.x, m1[0]); m1[1] = fmaf(sc1[l], v.y, m1[1]);
                m1[2] = fmaf(sc1[l], v.z, m1[2]); m1[3] = fmaf(sc1[l], v.w, m1[3]);
            }
        }
        __half2 h00 = __floats2half2_rn(m0[0], m0[1]);
        __half2 h01 = __floats2half2_rn(m0[2], m0[3]);
        __half2 h10 = __floats2half2_rn(m1[0], m1[1]);
        __half2 h11 = __floats2half2_rn(m1[2], m1[3]);
        *reinterpret_cast<__half2*>(&g_Mb[(size_t)s * 512 + e4])           = h00;
        *reinterpret_cast<__half2*>(&g_Mb[(size_t)s * 512 + e4 + 2])       = h01;
        *reinterpret_cast<__half2*>(&g_Mb[(size_t)s * 512 + 256 + e4])     = h10;
        *reinterpret_cast<__half2*>(&g_Mb[(size_t)s * 512 + 256 + e4 + 2]) = h11;
    }
}

// ======================= launch =======================

extern "C" void kernel_launch(void* const* d_in, const int* in_sizes, int n_in,
                              void* d_out, int out_size) {
    const float* msgs    = (const float*)d_in[0];
    const float* ts      = (const float*)d_in[1];
    const float* w_time  = (const float*)d_in[2];
    const float* b_time  = (const float*)d_in[3];
    const float* w_in    = (const float*)d_in[4];
    const float* b_in    = (const float*)d_in[5];
    const float* w_out   = (const float*)d_in[6];
    const float* b_out   = (const float*)d_in[7];
    const int*   lengths = (const int*)d_in[8];
    float* out = (float*)d_out;

    cudaFuncSetAttribute(gemm1_k, cudaFuncAttributeMaxDynamicSharedMemorySize, GEMM_SMEM);
    cudaFuncSetAttribute(gemm2_k, cudaFuncAttributeMaxDynamicSharedMemorySize, GEMM_SMEM);

    prep<<<4483, 256>>>(w_in, b_in, w_out, b_out, msgs);
    gemm1_k<<<dim3(128, 4), 256, GEMM_SMEM>>>();
    score_agg<<<2048, 256>>>(msgs, ts, w_time, b_time, lengths);
    gemm2_k<<<dim3(128, 2), 256, GEMM_SMEM>>>(out);
}